// round 6
// baseline (speedup 1.0000x reference)
#include <cuda_runtime.h>
#include <cuda_bf16.h>
#include <math.h>
#include <stdint.h>

// ---------------------------------------------------------------------------
// RelationalMemoryCell  (B=2048, S=8, H=8, M=1024, QKV=384, TOT=3072)
// Round 6: R5 + MMA dependency-chain fix (split-term outermost => 16
// independent MMAs between accumulator reuse) + earlier cp.async issue.
// ---------------------------------------------------------------------------

#define B_     2048
#define S_     8
#define H_     8
#define M_     1024
#define QKV_   384
#define TOT_   3072
#define SP1_   9
#define ROWS_  (B_*SP1_)   // 18432

typedef __nv_bfloat16  bf16;
typedef __nv_bfloat162 bf162;

// ---- global scratch (allocation-free rule) ----
__device__ __align__(256) float g_x   [(size_t)B_   * M_  ];
__device__ __align__(256) float g_qkv [(size_t)ROWS_* TOT_];
__device__ __align__(256) float g_m2  [(size_t)ROWS_* M_  ];
__device__ __align__(256) float g_gi  [(size_t)B_ * 2];

__device__ __align__(256) bf16 g_in_hi [(size_t)B_ * M_];
__device__ __align__(256) bf16 g_in_lo [(size_t)B_ * M_];
__device__ __align__(256) bf16 g_w_hi [(size_t)6 * M_ * M_];
__device__ __align__(256) bf16 g_w_lo [(size_t)6 * M_ * M_];
__device__ __align__(256) bf16 g_mpi_hi [(size_t)ROWS_ * M_];
__device__ __align__(256) bf16 g_mpi_lo [(size_t)ROWS_ * M_];
__device__ __align__(256) bf16 g_m1_hi  [(size_t)ROWS_ * M_];
__device__ __align__(256) bf16 g_m1_lo  [(size_t)ROWS_ * M_];
__device__ __align__(256) bf16 g_h_hi   [(size_t)ROWS_ * M_];
__device__ __align__(256) bf16 g_h_lo   [(size_t)ROWS_ * M_];

// ---------------------------------------------------------------------------
// helpers
// ---------------------------------------------------------------------------
__device__ __forceinline__ uint32_t smem_u32(const void* p) {
    uint32_t a;
    asm("{ .reg .u64 t; cvta.to.shared.u64 t, %1; cvt.u32.u64 %0, t; }"
        : "=r"(a) : "l"(p));
    return a;
}
__device__ __forceinline__ void cp16(uint32_t dst, const void* src) {
    asm volatile("cp.async.cg.shared.global [%0], [%1], 16;"
                 :: "r"(dst), "l"(src) : "memory");
}
#define CP_COMMIT() asm volatile("cp.async.commit_group;" ::: "memory")
#define CP_WAIT2()  asm volatile("cp.async.wait_group 2;"  ::: "memory")

__device__ __forceinline__ void ldsm4(uint32_t* r, uint32_t a) {
    asm volatile("ldmatrix.sync.aligned.m8n8.x4.shared.b16 {%0,%1,%2,%3}, [%4];"
        : "=r"(r[0]), "=r"(r[1]), "=r"(r[2]), "=r"(r[3]) : "r"(a));
}
__device__ __forceinline__ void ldsm4t(uint32_t* r, uint32_t a) {
    asm volatile("ldmatrix.sync.aligned.m8n8.x4.trans.shared.b16 {%0,%1,%2,%3}, [%4];"
        : "=r"(r[0]), "=r"(r[1]), "=r"(r[2]), "=r"(r[3]) : "r"(a));
}
__device__ __forceinline__ void mma16816(float* c, const uint32_t* a, const uint32_t* b) {
    asm volatile(
        "mma.sync.aligned.m16n8k16.row.col.f32.bf16.bf16.f32 "
        "{%0,%1,%2,%3}, {%4,%5,%6,%7}, {%8,%9}, {%0,%1,%2,%3};"
        : "+f"(c[0]), "+f"(c[1]), "+f"(c[2]), "+f"(c[3])
        : "r"(a[0]), "r"(a[1]), "r"(a[2]), "r"(a[3]), "r"(b[0]), "r"(b[1]));
}
__device__ __forceinline__ void split1(float v, bf16& hi, bf16& lo) {
    hi = __float2bfloat16_rn(v);
    lo = __float2bfloat16_rn(v - __bfloat162float(hi));
}

// ---------------------------------------------------------------------------
// split_kernel: fp32 -> (hi, lo) bf16, vectorized by 4.
// ---------------------------------------------------------------------------
__global__ void split_kernel(const float* __restrict__ src,
                             bf16* __restrict__ hi, bf16* __restrict__ lo,
                             int n4)
{
    int i = blockIdx.x * blockDim.x + threadIdx.x;
    if (i >= n4) return;
    float4 v = __ldg((const float4*)src + i);
    bf16 h0, h1, h2, h3, l0, l1, l2, l3;
    split1(v.x, h0, l0); split1(v.y, h1, l1);
    split1(v.z, h2, l2); split1(v.w, h3, l3);
    bf162* H = (bf162*)hi + 2 * i;
    bf162* L = (bf162*)lo + 2 * i;
    H[0] = bf162(h0, h1); H[1] = bf162(h2, h3);
    L[0] = bf162(l0, l1); L[1] = bf162(l2, l3);
}

// ---------------------------------------------------------------------------
// Split-bf16 HMMA GEMM, 256 threads (8 warps, 2x4 grid, 64x32 warp tile),
// 128x128 CTA tile, BK=32, 4-stage cp.async pipeline.
// MODE 0: fp32 out (+bias)
// MODE 1: relu(+bias) -> split bf16 out (Chi/Clo)
// MODE 2: fp32 out = (Rhi+Rlo) + (+bias)
// ---------------------------------------------------------------------------
#define AST     80u
#define BST     272u
#define OFF_ALO 10240u
#define OFF_BHI 20480u
#define OFF_BLO 29184u
#define BUFSZ   37888u
#define NSTAGE  4
#define DSMEM   (NSTAGE * 37888)

template<int MODE>
__global__ __launch_bounds__(256)
void hgemm_kernel(const bf16* __restrict__ Ahi, const bf16* __restrict__ Alo,
                  const bf16* __restrict__ Bhi, const bf16* __restrict__ Blo,
                  const float* __restrict__ bias,
                  const bf16* __restrict__ Rhi, const bf16* __restrict__ Rlo,
                  float* __restrict__ Cf,
                  bf16* __restrict__ Chi, bf16* __restrict__ Clo,
                  int N, int K)
{
    extern __shared__ char sm_[];
    const uint32_t sbase = smem_u32(sm_);

    const int tid  = threadIdx.x;
    const int wid  = tid >> 5;
    const int lane = tid & 31;
    const int wm   = (wid & 1) << 6;     // 0, 64
    const int wn   = (wid >> 1) << 5;    // 0, 32, 64, 96
    const int bm   = blockIdx.y << 7;
    const int bn   = blockIdx.x << 7;

    const int arow = tid >> 2, aseg = tid & 3;
    const int brow = tid >> 4, bseg = tid & 15;

    const bf16* ApH = Ahi + (size_t)(bm + arow) * K + (aseg << 3);
    const bf16* ApL = Alo + (size_t)(bm + arow) * K + (aseg << 3);
    const bf16* BpH = Bhi + (size_t)brow * N + bn + (bseg << 3);
    const bf16* BpL = Blo + (size_t)brow * N + bn + (bseg << 3);
    const uint32_t aDst = (uint32_t)arow * AST + (uint32_t)(aseg << 4);
    const uint32_t bDst = (uint32_t)brow * BST + (uint32_t)(bseg << 4);
    const size_t aRowStep = (size_t)64 * K;
    const uint32_t aDst2  = aDst + 64u * AST;
    const size_t bRowStep = (size_t)16 * N;
    const uint32_t bDst2  = bDst + 16u * BST;

    const int nchunk = K >> 5;

    float acc[4][4][4];
    #pragma unroll
    for (int i = 0; i < 4; i++)
        #pragma unroll
        for (int j = 0; j < 4; j++)
            #pragma unroll
            for (int k = 0; k < 4; k++) acc[i][j][k] = 0.f;

    // prologue: stages 0..NSTAGE-2
    #pragma unroll
    for (int s = 0; s < NSTAGE - 1; s++) {
        const uint32_t sb = sbase + (uint32_t)s * BUFSZ;
        cp16(sb + aDst,            ApH + (s << 5));
        cp16(sb + aDst2,           ApH + aRowStep + (s << 5));
        cp16(sb + OFF_ALO + aDst,  ApL + (s << 5));
        cp16(sb + OFF_ALO + aDst2, ApL + aRowStep + (s << 5));
        cp16(sb + OFF_BHI + bDst,  BpH + (size_t)(s << 5) * N);
        cp16(sb + OFF_BHI + bDst2, BpH + bRowStep + (size_t)(s << 5) * N);
        cp16(sb + OFF_BLO + bDst,  BpL + (size_t)(s << 5) * N);
        cp16(sb + OFF_BLO + bDst2, BpL + bRowStep + (size_t)(s << 5) * N);
        CP_COMMIT();
    }

    const uint32_t aOffBase = (uint32_t)(wm + (lane & 15)) * AST
                            + (uint32_t)((lane >> 4) << 4);
    const uint32_t bOffBase = (uint32_t)(lane & 15) * BST
                            + (uint32_t)(wn << 1) + (uint32_t)((lane >> 4) << 4);

    #pragma unroll 1
    for (int c = 0; c < nchunk; c++) {
        CP_WAIT2();
        __syncthreads();

        const uint32_t tb = sbase + (uint32_t)(c % NSTAGE) * BUFSZ;

        #pragma unroll
        for (int ks = 0; ks < 2; ks++) {
            uint32_t raH[4][4], raL[4][4], rbH[2][4], rbL[2][4];
            const uint32_t aAd = tb + aOffBase + (uint32_t)(ks << 5);
            #pragma unroll
            for (int mt = 0; mt < 4; mt++) {
                ldsm4(raH[mt], aAd + (uint32_t)(mt * 16) * AST);
                ldsm4(raL[mt], aAd + OFF_ALO + (uint32_t)(mt * 16) * AST);
            }
            const uint32_t bAd = tb + bOffBase + (uint32_t)(ks << 4) * BST;
            ldsm4t(rbH[0], bAd + OFF_BHI);
            ldsm4t(rbH[1], bAd + OFF_BHI + 32u);
            ldsm4t(rbL[0], bAd + OFF_BLO);
            ldsm4t(rbL[1], bAd + OFF_BLO + 32u);

            // issue next stage cp.async early (once per chunk, ks==0),
            // before the MMA block so LDGSTS overlaps tensor work
            if (ks == 0) {
                const int cn = c + NSTAGE - 1;
                if (cn < nchunk) {
                    const uint32_t nb = sbase + (uint32_t)(cn % NSTAGE) * BUFSZ;
                    cp16(nb + aDst,            ApH + (cn << 5));
                    cp16(nb + aDst2,           ApH + aRowStep + (cn << 5));
                    cp16(nb + OFF_ALO + aDst,  ApL + (cn << 5));
                    cp16(nb + OFF_ALO + aDst2, ApL + aRowStep + (cn << 5));
                    cp16(nb + OFF_BHI + bDst,  BpH + (size_t)(cn << 5) * N);
                    cp16(nb + OFF_BHI + bDst2, BpH + bRowStep + (size_t)(cn << 5) * N);
                    cp16(nb + OFF_BLO + bDst,  BpL + (size_t)(cn << 5) * N);
                    cp16(nb + OFF_BLO + bDst2, BpL + bRowStep + (size_t)(cn << 5) * N);
                }
                CP_COMMIT();
            }

            // split-term OUTERMOST: 16 independent MMAs between acc reuse
            #pragma unroll
            for (int s = 0; s < 3; s++) {
                #pragma unroll
                for (int mt = 0; mt < 4; mt++) {
                    const uint32_t* ra = (s == 2) ? raL[mt] : raH[mt];
                    #pragma unroll
                    for (int nt = 0; nt < 4; nt++) {
                        const uint32_t* rb = (s == 1)
                            ? &rbL[nt >> 1][(nt & 1) << 1]
                            : &rbH[nt >> 1][(nt & 1) << 1];
                        mma16816(acc[mt][nt], ra, rb);
                    }
                }
            }
        }
    }

    // ---- epilogue ----
    #pragma unroll
    for (int mt = 0; mt < 4; mt++) {
        #pragma unroll
        for (int nt = 0; nt < 4; nt++) {
            const int m = bm + wm + (mt << 4) + (lane >> 2);
            const int n = bn + wn + (nt << 3) + ((lane & 3) << 1);
            const float b0 = __ldg(&bias[n]);
            const float b1 = __ldg(&bias[n + 1]);
            float2 v0, v1;
            v0.x = acc[mt][nt][0] + b0;  v0.y = acc[mt][nt][1] + b1;
            v1.x = acc[mt][nt][2] + b0;  v1.y = acc[mt][nt][3] + b1;
            const size_t i0 = (size_t)m * N + n;
            const size_t i1 = (size_t)(m + 8) * N + n;
            if (MODE == 0) {
                *(float2*)(Cf + i0) = v0;
                *(float2*)(Cf + i1) = v1;
            }
            if (MODE == 1) {
                v0.x = fmaxf(v0.x, 0.f); v0.y = fmaxf(v0.y, 0.f);
                v1.x = fmaxf(v1.x, 0.f); v1.y = fmaxf(v1.y, 0.f);
                bf16 h0, h1, l0, l1;
                split1(v0.x, h0, l0); split1(v0.y, h1, l1);
                *(bf162*)(Chi + i0) = bf162(h0, h1);
                *(bf162*)(Clo + i0) = bf162(l0, l1);
                split1(v1.x, h0, l0); split1(v1.y, h1, l1);
                *(bf162*)(Chi + i1) = bf162(h0, h1);
                *(bf162*)(Clo + i1) = bf162(l0, l1);
            }
            if (MODE == 2) {
                bf162 rh0 = *(const bf162*)(Rhi + i0);
                bf162 rl0 = *(const bf162*)(Rlo + i0);
                bf162 rh1 = *(const bf162*)(Rhi + i1);
                bf162 rl1 = *(const bf162*)(Rlo + i1);
                v0.x += __bfloat162float(rh0.x) + __bfloat162float(rl0.x);
                v0.y += __bfloat162float(rh0.y) + __bfloat162float(rl0.y);
                v1.x += __bfloat162float(rh1.x) + __bfloat162float(rl1.x);
                v1.y += __bfloat162float(rh1.y) + __bfloat162float(rl1.y);
                *(float2*)(Cf + i0) = v0;
                *(float2*)(Cf + i1) = v1;
            }
        }
    }
}

// ---------------------------------------------------------------------------
// mpi(hi/lo) = split(concat(memory, x))
// ---------------------------------------------------------------------------
__global__ void build_mpi_kernel(const float* __restrict__ mem,
                                 const float* __restrict__ x,
                                 bf16* __restrict__ hi, bf16* __restrict__ lo)
{
    size_t i = (size_t)blockIdx.x * blockDim.x + threadIdx.x;
    int    mp  = (int)(i & 511);
    size_t row = i >> 9;
    size_t b   = row / SP1_;
    int    s   = (int)(row - b * SP1_);
    const float* src = (s < S_) ? (mem + ((b * S_ + s) << 10)) : (x + (b << 10));
    float2 v = *(const float2*)(src + (mp << 1));
    bf16 h0, h1, l0, l1;
    split1(v.x, h0, l0); split1(v.y, h1, l1);
    ((bf162*)hi)[i] = bf162(h0, h1);
    ((bf162*)lo)[i] = bf162(l0, l1);
}

// ---------------------------------------------------------------------------
// gi[b,0:2] = x[b,:] @ kernel_gi + bias_gi
// ---------------------------------------------------------------------------
__global__ void gi_kernel(const float* __restrict__ x,
                          const float* __restrict__ kgi,
                          const float* __restrict__ bgi,
                          float* __restrict__ gi)
{
    int b    = blockIdx.x * 8 + (threadIdx.x >> 5);
    int lane = threadIdx.x & 31;
    const float* xr = x + (size_t)b * M_;
    float g0 = 0.f, g1 = 0.f;
    for (int m = lane; m < M_; m += 32) {
        float xv = xr[m];
        g0 = fmaf(xv, kgi[2 * m + 0], g0);
        g1 = fmaf(xv, kgi[2 * m + 1], g1);
    }
    #pragma unroll
    for (int o = 16; o; o >>= 1) {
        g0 += __shfl_xor_sync(0xffffffffu, g0, o);
        g1 += __shfl_xor_sync(0xffffffffu, g1, o);
    }
    if (lane == 0) {
        gi[2 * b + 0] = g0 + bgi[0];
        gi[2 * b + 1] = g1 + bgi[1];
    }
}

// ---------------------------------------------------------------------------
// Attention per (b,h):  m1 = (mpi_hi+mpi_lo) + softmax(q k^T) v -> split out
// ---------------------------------------------------------------------------
__global__ __launch_bounds__(256)
void attn_kernel(const float* __restrict__ qkv,
                 const bf16* __restrict__ mpihi, const bf16* __restrict__ mpilo,
                 bf16* __restrict__ m1hi, bf16* __restrict__ m1lo)
{
    const int bh = blockIdx.x;
    const int b  = bh >> 3;
    const int h  = bh & 7;

    __shared__ float q [SP1_][128];
    __shared__ float kk[SP1_][128];
    __shared__ float vv[SP1_][128];
    __shared__ float sc[SP1_][SP1_];

    const float scale = rsqrtf((float)QKV_);
    const int tid = threadIdx.x;

    for (int i = tid; i < SP1_ * 128; i += 256) {
        int s = i >> 7, d = i & 127;
        const float* base = qkv + ((size_t)(b * SP1_ + s)) * TOT_ + h * QKV_;
        q [s][d] = base[d] * scale;
        kk[s][d] = base[128 + d];
        vv[s][d] = base[256 + d];
    }
    __syncthreads();

    const int w = tid >> 5, lane = tid & 31;
    for (int idx = w; idx < SP1_ * SP1_; idx += 8) {
        int i = idx / SP1_, j = idx - i * SP1_;
        float s = 0.f;
        for (int d = lane; d < 128; d += 32) s = fmaf(q[i][d], kk[j][d], s);
        #pragma unroll
        for (int o = 16; o; o >>= 1) s += __shfl_xor_sync(0xffffffffu, s, o);
        if (lane == 0) sc[i][j] = s;
    }
    __syncthreads();

    if (tid < SP1_) {
        float mx = -1e30f;
        #pragma unroll
        for (int j = 0; j < SP1_; j++) mx = fmaxf(mx, sc[tid][j]);
        float e[SP1_], sum = 0.f;
        #pragma unroll
        for (int j = 0; j < SP1_; j++) { e[j] = expf(sc[tid][j] - mx); sum += e[j]; }
        float inv = 1.f / sum;
        #pragma unroll
        for (int j = 0; j < SP1_; j++) sc[tid][j] = e[j] * inv;
    }
    __syncthreads();

    for (int i = tid; i < SP1_ * 64; i += 256) {
        int s  = i >> 6;
        int d  = (i & 63) << 1;
        float a0 = 0.f, a1 = 0.f;
        #pragma unroll
        for (int j = 0; j < SP1_; j++) {
            a0 = fmaf(sc[s][j], vv[j][d],     a0);
            a1 = fmaf(sc[s][j], vv[j][d + 1], a1);
        }
        size_t o = ((size_t)(b * SP1_ + s)) * M_ + h * 128 + d;
        bf162 mh = *(const bf162*)(mpihi + o);
        bf162 ml = *(const bf162*)(mpilo + o);
        float v0 = __bfloat162float(mh.x) + __bfloat162float(ml.x) + a0;
        float v1 = __bfloat162float(mh.y) + __bfloat162float(ml.y) + a1;
        bf16 h0, h1, l0, l1;
        split1(v0, h0, l0); split1(v1, h1, l1);
        *(bf162*)(m1hi + o) = bf162(h0, h1);
        *(bf162*)(m1lo + o) = bf162(l0, l1);
    }
}

// ---------------------------------------------------------------------------
// Gate epilogue per (b,s)
// ---------------------------------------------------------------------------
__global__ __launch_bounds__(256)
void gate_kernel(const float* __restrict__ mem,
                 const float* __restrict__ m2,
                 const float* __restrict__ kgm,
                 const float* __restrict__ bgm,
                 const float* __restrict__ gi,
                 float* __restrict__ out)
{
    const int bs = blockIdx.x;
    const int b  = bs >> 3;
    const int s  = bs & 7;
    const int tid = threadIdx.x;

    const float* mrow  = mem + (size_t)bs * M_;
    const float* m2row = m2  + ((size_t)(b * SP1_ + s)) * M_;

    float g0 = 0.f, g1 = 0.f;
    for (int m = tid; m < M_; m += 256) {
        float t = tanhf(mrow[m]);
        g0 = fmaf(t, kgm[2 * m + 0], g0);
        g1 = fmaf(t, kgm[2 * m + 1], g1);
    }
    #pragma unroll
    for (int o = 16; o; o >>= 1) {
        g0 += __shfl_xor_sync(0xffffffffu, g0, o);
        g1 += __shfl_xor_sync(0xffffffffu, g1, o);
    }
    __shared__ float s0[8], s1[8];
    __shared__ float igs, fgs;
    int w = tid >> 5, lane = tid & 31;
    if (lane == 0) { s0[w] = g0; s1[w] = g1; }
    __syncthreads();
    if (tid == 0) {
        float G0 = 0.f, G1 = 0.f;
        #pragma unroll
        for (int i = 0; i < 8; i++) { G0 += s0[i]; G1 += s1[i]; }
        G0 += bgm[0] + gi[2 * b + 0];
        G1 += bgm[1] + gi[2 * b + 1] + 1.0f;
        igs = 1.f / (1.f + expf(-G0));
        fgs = 1.f / (1.f + expf(-G1));
    }
    __syncthreads();
    const float ig = igs, fg = fgs;

    float* orow = out + (size_t)b * (S_ * M_) + s * M_;
    for (int m = tid; m < M_; m += 256) {
        orow[m] = fmaf(ig, tanhf(m2row[m]), fg * mrow[m]);
    }
}

// ---------------------------------------------------------------------------
// kernel_launch
// ---------------------------------------------------------------------------
extern "C" void kernel_launch(void* const* d_in, const int* in_sizes, int n_in,
                              void* d_out, int out_size)
{
    const float* inputs   = (const float*)d_in[0];
    const float* memory   = (const float*)d_in[1];
    const float* k_qkv    = (const float*)d_in[2];
    const float* b_qkv    = (const float*)d_in[3];
    const float* k_gi     = (const float*)d_in[4];
    const float* b_gi     = (const float*)d_in[5];
    const float* k_gm     = (const float*)d_in[6];
    const float* b_gm     = (const float*)d_in[7];
    const float* k_in     = (const float*)d_in[8];
    const float* b_in     = (const float*)d_in[9];
    const float* mlp_k0   = (const float*)d_in[10];
    const float* mlp_b0   = (const float*)d_in[11];
    const float* mlp_k1   = (const float*)d_in[12];
    const float* mlp_b1   = (const float*)d_in[13];
    float* out = (float*)d_out;

    float *px, *pqkv, *pm2, *pgi;
    bf16 *pinh, *pinl, *pwh, *pwl, *pmpih, *pmpil, *pm1h, *pm1l, *phh, *phl;
    cudaGetSymbolAddress((void**)&px,    g_x);
    cudaGetSymbolAddress((void**)&pqkv,  g_qkv);
    cudaGetSymbolAddress((void**)&pm2,   g_m2);
    cudaGetSymbolAddress((void**)&pgi,   g_gi);
    cudaGetSymbolAddress((void**)&pinh,  g_in_hi);
    cudaGetSymbolAddress((void**)&pinl,  g_in_lo);
    cudaGetSymbolAddress((void**)&pwh,   g_w_hi);
    cudaGetSymbolAddress((void**)&pwl,   g_w_lo);
    cudaGetSymbolAddress((void**)&pmpih, g_mpi_hi);
    cudaGetSymbolAddress((void**)&pmpil, g_mpi_lo);
    cudaGetSymbolAddress((void**)&pm1h,  g_m1_hi);
    cudaGetSymbolAddress((void**)&pm1l,  g_m1_lo);
    cudaGetSymbolAddress((void**)&phh,   g_h_hi);
    cudaGetSymbolAddress((void**)&phl,   g_h_lo);

    const size_t MM = (size_t)M_ * M_;
    bf16 *kinH = pwh,          *kinL = pwl;
    bf16 *kqkH = pwh + MM,     *kqkL = pwl + MM;
    bf16 *k0H  = pwh + 4 * MM, *k0L  = pwl + 4 * MM;
    bf16 *k1H  = pwh + 5 * MM, *k1L  = pwl + 5 * MM;

    cudaFuncSetAttribute(hgemm_kernel<0>, cudaFuncAttributeMaxDynamicSharedMemorySize, DSMEM);
    cudaFuncSetAttribute(hgemm_kernel<1>, cudaFuncAttributeMaxDynamicSharedMemorySize, DSMEM);
    cudaFuncSetAttribute(hgemm_kernel<2>, cudaFuncAttributeMaxDynamicSharedMemorySize, DSMEM);

    // 0. split weights + inputs
    split_kernel<<<(B_ * M_ / 4 + 255) / 256, 256>>>(inputs, pinh, pinl, B_ * M_ / 4);
    split_kernel<<<(int)((MM / 4 + 255) / 256), 256>>>(k_in,   kinH, kinL, (int)(MM / 4));
    split_kernel<<<(int)((3 * MM / 4 + 255) / 256), 256>>>(k_qkv, kqkH, kqkL, (int)(3 * MM / 4));
    split_kernel<<<(int)((MM / 4 + 255) / 256), 256>>>(mlp_k0, k0H, k0L, (int)(MM / 4));
    split_kernel<<<(int)((MM / 4 + 255) / 256), 256>>>(mlp_k1, k1H, k1L, (int)(MM / 4));

    // 1. x = inputs @ kernel_in + bias_in
    hgemm_kernel<0><<<dim3(M_ / 128, B_ / 128), 256, DSMEM>>>(
        pinh, pinl, kinH, kinL, b_in, nullptr, nullptr, px, nullptr, nullptr, M_, M_);

    // 2. mpi (split)
    build_mpi_kernel<<<(unsigned)(((size_t)ROWS_ * M_ / 2) / 256), 256>>>(
        memory, px, pmpih, pmpil);

    // 3. gi
    gi_kernel<<<B_ / 8, 256>>>(px, k_gi, b_gi, pgi);

    // 4. qkv = mpi @ kernel_qkv + bias_qkv
    hgemm_kernel<0><<<dim3(TOT_ / 128, ROWS_ / 128), 256, DSMEM>>>(
        pmpih, pmpil, kqkH, kqkL, b_qkv, nullptr, nullptr, pqkv, nullptr, nullptr, TOT_, M_);

    // 5. attention + residual -> m1 (split)
    attn_kernel<<<B_ * H_, 256>>>(pqkv, pmpih, pmpil, pm1h, pm1l);

    // 6. h = relu(m1 @ mlp_k0 + mlp_b0) -> split
    hgemm_kernel<1><<<dim3(M_ / 128, ROWS_ / 128), 256, DSMEM>>>(
        pm1h, pm1l, k0H, k0L, mlp_b0, nullptr, nullptr, nullptr, phh, phl, M_, M_);

    // 7. m2 = m1 + h @ mlp_k1 + mlp_b1
    hgemm_kernel<2><<<dim3(M_ / 128, ROWS_ / 128), 256, DSMEM>>>(
        phh, phl, k1H, k1L, mlp_b1, pm1h, pm1l, pm2, nullptr, nullptr, M_, M_);

    // 8. gates + output
    gate_kernel<<<B_ * S_, 256>>>(memory, pm2, k_gm, b_gm, pgi, out);
}

// round 7
// speedup vs baseline: 1.4132x; 1.4132x over previous
#include <cuda_runtime.h>
#include <cuda_bf16.h>
#include <math.h>
#include <stdint.h>

// ---------------------------------------------------------------------------
// RelationalMemoryCell  (B=2048, S=8, H=8, M=1024, QKV=384, TOT=3072)
// Round 7: R4 substrate (512 thr, 4x4 warps, 3-stage cp.async) +
//   split-term-outermost MMA ordering (16 independent MMAs between acc reuse)
//   + next-stage cp.async issued before the MMA wall.
// A@B ~= AhBh + AhBl + AlBh (fp32 accumulate).
// ---------------------------------------------------------------------------

#define B_     2048
#define S_     8
#define H_     8
#define M_     1024
#define QKV_   384
#define TOT_   3072
#define SP1_   9
#define ROWS_  (B_*SP1_)   // 18432

typedef __nv_bfloat16  bf16;
typedef __nv_bfloat162 bf162;

// ---- global scratch (allocation-free rule) ----
__device__ __align__(256) float g_x   [(size_t)B_   * M_  ];
__device__ __align__(256) float g_qkv [(size_t)ROWS_* TOT_];
__device__ __align__(256) float g_m2  [(size_t)ROWS_* M_  ];
__device__ __align__(256) float g_gi  [(size_t)B_ * 2];

__device__ __align__(256) bf16 g_in_hi [(size_t)B_ * M_];
__device__ __align__(256) bf16 g_in_lo [(size_t)B_ * M_];
__device__ __align__(256) bf16 g_w_hi [(size_t)6 * M_ * M_];
__device__ __align__(256) bf16 g_w_lo [(size_t)6 * M_ * M_];
__device__ __align__(256) bf16 g_mpi_hi [(size_t)ROWS_ * M_];
__device__ __align__(256) bf16 g_mpi_lo [(size_t)ROWS_ * M_];
__device__ __align__(256) bf16 g_m1_hi  [(size_t)ROWS_ * M_];
__device__ __align__(256) bf16 g_m1_lo  [(size_t)ROWS_ * M_];
__device__ __align__(256) bf16 g_h_hi   [(size_t)ROWS_ * M_];
__device__ __align__(256) bf16 g_h_lo   [(size_t)ROWS_ * M_];

// ---------------------------------------------------------------------------
// helpers
// ---------------------------------------------------------------------------
__device__ __forceinline__ uint32_t smem_u32(const void* p) {
    uint32_t a;
    asm("{ .reg .u64 t; cvta.to.shared.u64 t, %1; cvt.u32.u64 %0, t; }"
        : "=r"(a) : "l"(p));
    return a;
}
__device__ __forceinline__ void cp16(uint32_t dst, const void* src) {
    asm volatile("cp.async.cg.shared.global [%0], [%1], 16;"
                 :: "r"(dst), "l"(src) : "memory");
}
#define CP_COMMIT() asm volatile("cp.async.commit_group;" ::: "memory")
#define CP_WAIT1()  asm volatile("cp.async.wait_group 1;"  ::: "memory")

__device__ __forceinline__ void ldsm4(uint32_t* r, uint32_t a) {
    asm volatile("ldmatrix.sync.aligned.m8n8.x4.shared.b16 {%0,%1,%2,%3}, [%4];"
        : "=r"(r[0]), "=r"(r[1]), "=r"(r[2]), "=r"(r[3]) : "r"(a));
}
__device__ __forceinline__ void ldsm4t(uint32_t* r, uint32_t a) {
    asm volatile("ldmatrix.sync.aligned.m8n8.x4.trans.shared.b16 {%0,%1,%2,%3}, [%4];"
        : "=r"(r[0]), "=r"(r[1]), "=r"(r[2]), "=r"(r[3]) : "r"(a));
}
__device__ __forceinline__ void mma16816(float* c, const uint32_t* a, const uint32_t* b) {
    asm volatile(
        "mma.sync.aligned.m16n8k16.row.col.f32.bf16.bf16.f32 "
        "{%0,%1,%2,%3}, {%4,%5,%6,%7}, {%8,%9}, {%0,%1,%2,%3};"
        : "+f"(c[0]), "+f"(c[1]), "+f"(c[2]), "+f"(c[3])
        : "r"(a[0]), "r"(a[1]), "r"(a[2]), "r"(a[3]), "r"(b[0]), "r"(b[1]));
}
__device__ __forceinline__ void split1(float v, bf16& hi, bf16& lo) {
    hi = __float2bfloat16_rn(v);
    lo = __float2bfloat16_rn(v - __bfloat162float(hi));
}

// ---------------------------------------------------------------------------
// split_kernel: fp32 -> (hi, lo) bf16, vectorized by 4.
// ---------------------------------------------------------------------------
__global__ void split_kernel(const float* __restrict__ src,
                             bf16* __restrict__ hi, bf16* __restrict__ lo,
                             int n4)
{
    int i = blockIdx.x * blockDim.x + threadIdx.x;
    if (i >= n4) return;
    float4 v = __ldg((const float4*)src + i);
    bf16 h0, h1, h2, h3, l0, l1, l2, l3;
    split1(v.x, h0, l0); split1(v.y, h1, l1);
    split1(v.z, h2, l2); split1(v.w, h3, l3);
    bf162* H = (bf162*)hi + 2 * i;
    bf162* L = (bf162*)lo + 2 * i;
    H[0] = bf162(h0, h1); H[1] = bf162(h2, h3);
    L[0] = bf162(l0, l1); L[1] = bf162(l2, l3);
}

// ---------------------------------------------------------------------------
// Split-bf16 HMMA GEMM, 512 threads (16 warps, 4x4 grid, 32x32 warp tile),
// 128x128 CTA tile, BK=32, 3-stage cp.async pipeline.
// MODE 0: fp32 out (+bias)
// MODE 1: relu(+bias) -> split bf16 out (Chi/Clo)
// MODE 2: fp32 out = (Rhi+Rlo) + (+bias)
// ---------------------------------------------------------------------------
#define AST     80u
#define BST     272u
#define OFF_ALO 10240u
#define OFF_BHI 20480u
#define OFF_BLO 29184u
#define BUFSZ   37888u
#define NSTAGE  3
#define DSMEM   (NSTAGE * 37888)

template<int MODE>
__global__ __launch_bounds__(512)
void hgemm_kernel(const bf16* __restrict__ Ahi, const bf16* __restrict__ Alo,
                  const bf16* __restrict__ Bhi, const bf16* __restrict__ Blo,
                  const float* __restrict__ bias,
                  const bf16* __restrict__ Rhi, const bf16* __restrict__ Rlo,
                  float* __restrict__ Cf,
                  bf16* __restrict__ Chi, bf16* __restrict__ Clo,
                  int N, int K)
{
    extern __shared__ char sm_[];
    const uint32_t sbase = smem_u32(sm_);

    const int tid  = threadIdx.x;
    const int wid  = tid >> 5;
    const int lane = tid & 31;
    const int wm   = (wid & 3) << 5;     // 0,32,64,96
    const int wn   = (wid >> 2) << 5;    // 0,32,64,96
    const int bm   = blockIdx.y << 7;
    const int bn   = blockIdx.x << 7;

    // loader slots: A 128 rows x 4 segs of 16B; B 32 rows x 16 segs of 16B
    const int arow = tid >> 2, aseg = tid & 3;
    const int brow = tid >> 4, bseg = tid & 15;

    const bf16* ApH = Ahi + (size_t)(bm + arow) * K + (aseg << 3);
    const bf16* ApL = Alo + (size_t)(bm + arow) * K + (aseg << 3);
    const bf16* BpH = Bhi + (size_t)brow * N + bn + (bseg << 3);
    const bf16* BpL = Blo + (size_t)brow * N + bn + (bseg << 3);
    const uint32_t aDst = (uint32_t)arow * AST + (uint32_t)(aseg << 4);
    const uint32_t bDst = (uint32_t)brow * BST + (uint32_t)(bseg << 4);

    const int nchunk = K >> 5;

    float acc[2][4][4];
    #pragma unroll
    for (int i = 0; i < 2; i++)
        #pragma unroll
        for (int j = 0; j < 4; j++)
            #pragma unroll
            for (int k = 0; k < 4; k++) acc[i][j][k] = 0.f;

    // prologue: stages 0, 1
    #pragma unroll
    for (int s = 0; s < NSTAGE - 1; s++) {
        const uint32_t sb = sbase + (uint32_t)s * BUFSZ;
        cp16(sb + aDst,           ApH + (s << 5));
        cp16(sb + OFF_ALO + aDst, ApL + (s << 5));
        cp16(sb + OFF_BHI + bDst, BpH + (size_t)(s << 5) * N);
        cp16(sb + OFF_BLO + bDst, BpL + (size_t)(s << 5) * N);
        CP_COMMIT();
    }

    const uint32_t aOffBase = (uint32_t)(wm + (lane & 15)) * AST
                            + (uint32_t)((lane >> 4) << 4);
    const uint32_t bOffBase = (uint32_t)(lane & 15) * BST
                            + (uint32_t)(wn << 1) + (uint32_t)((lane >> 4) << 4);

    #pragma unroll 1
    for (int c = 0; c < nchunk; c++) {
        CP_WAIT1();
        __syncthreads();

        const uint32_t tb = sbase + (uint32_t)(c % NSTAGE) * BUFSZ;

        #pragma unroll
        for (int ks = 0; ks < 2; ks++) {
            uint32_t raH[2][4], raL[2][4], rbH[2][4], rbL[2][4];
            const uint32_t aAd = tb + aOffBase + (uint32_t)(ks << 5);
            ldsm4(raH[0], aAd);
            ldsm4(raH[1], aAd + 16u * AST);
            ldsm4(raL[0], aAd + OFF_ALO);
            ldsm4(raL[1], aAd + OFF_ALO + 16u * AST);
            const uint32_t bAd = tb + bOffBase + (uint32_t)(ks << 4) * BST;
            ldsm4t(rbH[0], bAd + OFF_BHI);
            ldsm4t(rbH[1], bAd + OFF_BHI + 32u);
            ldsm4t(rbL[0], bAd + OFF_BLO);
            ldsm4t(rbL[1], bAd + OFF_BLO + 32u);

            // issue next stage before the MMA wall (once per chunk)
            if (ks == 0) {
                const int cn = c + NSTAGE - 1;
                if (cn < nchunk) {
                    const uint32_t nb = sbase + (uint32_t)(cn % NSTAGE) * BUFSZ;
                    cp16(nb + aDst,           ApH + (cn << 5));
                    cp16(nb + OFF_ALO + aDst, ApL + (cn << 5));
                    cp16(nb + OFF_BHI + bDst, BpH + (size_t)(cn << 5) * N);
                    cp16(nb + OFF_BLO + bDst, BpL + (size_t)(cn << 5) * N);
                }
                CP_COMMIT();
            }

            // split-term OUTERMOST: 16 independent MMAs between acc reuse
            #pragma unroll
            for (int s = 0; s < 3; s++) {
                #pragma unroll
                for (int mt = 0; mt < 2; mt++) {
                    const uint32_t* ra = (s == 2) ? raL[mt] : raH[mt];
                    #pragma unroll
                    for (int nt = 0; nt < 4; nt++) {
                        const uint32_t* rb = (s == 1)
                            ? &rbL[nt >> 1][(nt & 1) << 1]
                            : &rbH[nt >> 1][(nt & 1) << 1];
                        mma16816(acc[mt][nt], ra, rb);
                    }
                }
            }
        }
    }

    // ---- epilogue ----
    #pragma unroll
    for (int mt = 0; mt < 2; mt++) {
        #pragma unroll
        for (int nt = 0; nt < 4; nt++) {
            const int m = bm + wm + (mt << 4) + (lane >> 2);
            const int n = bn + wn + (nt << 3) + ((lane & 3) << 1);
            const float b0 = __ldg(&bias[n]);
            const float b1 = __ldg(&bias[n + 1]);
            float2 v0, v1;
            v0.x = acc[mt][nt][0] + b0;  v0.y = acc[mt][nt][1] + b1;
            v1.x = acc[mt][nt][2] + b0;  v1.y = acc[mt][nt][3] + b1;
            const size_t i0 = (size_t)m * N + n;
            const size_t i1 = (size_t)(m + 8) * N + n;
            if (MODE == 0) {
                *(float2*)(Cf + i0) = v0;
                *(float2*)(Cf + i1) = v1;
            }
            if (MODE == 1) {
                v0.x = fmaxf(v0.x, 0.f); v0.y = fmaxf(v0.y, 0.f);
                v1.x = fmaxf(v1.x, 0.f); v1.y = fmaxf(v1.y, 0.f);
                bf16 h0, h1, l0, l1;
                split1(v0.x, h0, l0); split1(v0.y, h1, l1);
                *(bf162*)(Chi + i0) = bf162(h0, h1);
                *(bf162*)(Clo + i0) = bf162(l0, l1);
                split1(v1.x, h0, l0); split1(v1.y, h1, l1);
                *(bf162*)(Chi + i1) = bf162(h0, h1);
                *(bf162*)(Clo + i1) = bf162(l0, l1);
            }
            if (MODE == 2) {
                bf162 rh0 = *(const bf162*)(Rhi + i0);
                bf162 rl0 = *(const bf162*)(Rlo + i0);
                bf162 rh1 = *(const bf162*)(Rhi + i1);
                bf162 rl1 = *(const bf162*)(Rlo + i1);
                v0.x += __bfloat162float(rh0.x) + __bfloat162float(rl0.x);
                v0.y += __bfloat162float(rh0.y) + __bfloat162float(rl0.y);
                v1.x += __bfloat162float(rh1.x) + __bfloat162float(rl1.x);
                v1.y += __bfloat162float(rh1.y) + __bfloat162float(rl1.y);
                *(float2*)(Cf + i0) = v0;
                *(float2*)(Cf + i1) = v1;
            }
        }
    }
}

// ---------------------------------------------------------------------------
// mpi(hi/lo) = split(concat(memory, x))
// ---------------------------------------------------------------------------
__global__ void build_mpi_kernel(const float* __restrict__ mem,
                                 const float* __restrict__ x,
                                 bf16* __restrict__ hi, bf16* __restrict__ lo)
{
    size_t i = (size_t)blockIdx.x * blockDim.x + threadIdx.x;
    int    mp  = (int)(i & 511);
    size_t row = i >> 9;
    size_t b   = row / SP1_;
    int    s   = (int)(row - b * SP1_);
    const float* src = (s < S_) ? (mem + ((b * S_ + s) << 10)) : (x + (b << 10));
    float2 v = *(const float2*)(src + (mp << 1));
    bf16 h0, h1, l0, l1;
    split1(v.x, h0, l0); split1(v.y, h1, l1);
    ((bf162*)hi)[i] = bf162(h0, h1);
    ((bf162*)lo)[i] = bf162(l0, l1);
}

// ---------------------------------------------------------------------------
// gi[b,0:2] = x[b,:] @ kernel_gi + bias_gi
// ---------------------------------------------------------------------------
__global__ void gi_kernel(const float* __restrict__ x,
                          const float* __restrict__ kgi,
                          const float* __restrict__ bgi,
                          float* __restrict__ gi)
{
    int b    = blockIdx.x * 8 + (threadIdx.x >> 5);
    int lane = threadIdx.x & 31;
    const float* xr = x + (size_t)b * M_;
    float g0 = 0.f, g1 = 0.f;
    for (int m = lane; m < M_; m += 32) {
        float xv = xr[m];
        g0 = fmaf(xv, kgi[2 * m + 0], g0);
        g1 = fmaf(xv, kgi[2 * m + 1], g1);
    }
    #pragma unroll
    for (int o = 16; o; o >>= 1) {
        g0 += __shfl_xor_sync(0xffffffffu, g0, o);
        g1 += __shfl_xor_sync(0xffffffffu, g1, o);
    }
    if (lane == 0) {
        gi[2 * b + 0] = g0 + bgi[0];
        gi[2 * b + 1] = g1 + bgi[1];
    }
}

// ---------------------------------------------------------------------------
// Attention per (b,h):  m1 = (mpi_hi+mpi_lo) + softmax(q k^T) v -> split out
// ---------------------------------------------------------------------------
__global__ __launch_bounds__(256)
void attn_kernel(const float* __restrict__ qkv,
                 const bf16* __restrict__ mpihi, const bf16* __restrict__ mpilo,
                 bf16* __restrict__ m1hi, bf16* __restrict__ m1lo)
{
    const int bh = blockIdx.x;
    const int b  = bh >> 3;
    const int h  = bh & 7;

    __shared__ float q [SP1_][128];
    __shared__ float kk[SP1_][128];
    __shared__ float vv[SP1_][128];
    __shared__ float sc[SP1_][SP1_];

    const float scale = rsqrtf((float)QKV_);
    const int tid = threadIdx.x;

    for (int i = tid; i < SP1_ * 128; i += 256) {
        int s = i >> 7, d = i & 127;
        const float* base = qkv + ((size_t)(b * SP1_ + s)) * TOT_ + h * QKV_;
        q [s][d] = base[d] * scale;
        kk[s][d] = base[128 + d];
        vv[s][d] = base[256 + d];
    }
    __syncthreads();

    const int w = tid >> 5, lane = tid & 31;
    for (int idx = w; idx < SP1_ * SP1_; idx += 8) {
        int i = idx / SP1_, j = idx - i * SP1_;
        float s = 0.f;
        for (int d = lane; d < 128; d += 32) s = fmaf(q[i][d], kk[j][d], s);
        #pragma unroll
        for (int o = 16; o; o >>= 1) s += __shfl_xor_sync(0xffffffffu, s, o);
        if (lane == 0) sc[i][j] = s;
    }
    __syncthreads();

    if (tid < SP1_) {
        float mx = -1e30f;
        #pragma unroll
        for (int j = 0; j < SP1_; j++) mx = fmaxf(mx, sc[tid][j]);
        float e[SP1_], sum = 0.f;
        #pragma unroll
        for (int j = 0; j < SP1_; j++) { e[j] = expf(sc[tid][j] - mx); sum += e[j]; }
        float inv = 1.f / sum;
        #pragma unroll
        for (int j = 0; j < SP1_; j++) sc[tid][j] = e[j] * inv;
    }
    __syncthreads();

    for (int i = tid; i < SP1_ * 64; i += 256) {
        int s  = i >> 6;
        int d  = (i & 63) << 1;
        float a0 = 0.f, a1 = 0.f;
        #pragma unroll
        for (int j = 0; j < SP1_; j++) {
            a0 = fmaf(sc[s][j], vv[j][d],     a0);
            a1 = fmaf(sc[s][j], vv[j][d + 1], a1);
        }
        size_t o = ((size_t)(b * SP1_ + s)) * M_ + h * 128 + d;
        bf162 mh = *(const bf162*)(mpihi + o);
        bf162 ml = *(const bf162*)(mpilo + o);
        float v0 = __bfloat162float(mh.x) + __bfloat162float(ml.x) + a0;
        float v1 = __bfloat162float(mh.y) + __bfloat162float(ml.y) + a1;
        bf16 h0, h1, l0, l1;
        split1(v0, h0, l0); split1(v1, h1, l1);
        *(bf162*)(m1hi + o) = bf162(h0, h1);
        *(bf162*)(m1lo + o) = bf162(l0, l1);
    }
}

// ---------------------------------------------------------------------------
// Gate epilogue per (b,s)
// ---------------------------------------------------------------------------
__global__ __launch_bounds__(256)
void gate_kernel(const float* __restrict__ mem,
                 const float* __restrict__ m2,
                 const float* __restrict__ kgm,
                 const float* __restrict__ bgm,
                 const float* __restrict__ gi,
                 float* __restrict__ out)
{
    const int bs = blockIdx.x;
    const int b  = bs >> 3;
    const int s  = bs & 7;
    const int tid = threadIdx.x;

    const float* mrow  = mem + (size_t)bs * M_;
    const float* m2row = m2  + ((size_t)(b * SP1_ + s)) * M_;

    float g0 = 0.f, g1 = 0.f;
    for (int m = tid; m < M_; m += 256) {
        float t = tanhf(mrow[m]);
        g0 = fmaf(t, kgm[2 * m + 0], g0);
        g1 = fmaf(t, kgm[2 * m + 1], g1);
    }
    #pragma unroll
    for (int o = 16; o; o >>= 1) {
        g0 += __shfl_xor_sync(0xffffffffu, g0, o);
        g1 += __shfl_xor_sync(0xffffffffu, g1, o);
    }
    __shared__ float s0[8], s1[8];
    __shared__ float igs, fgs;
    int w = tid >> 5, lane = tid & 31;
    if (lane == 0) { s0[w] = g0; s1[w] = g1; }
    __syncthreads();
    if (tid == 0) {
        float G0 = 0.f, G1 = 0.f;
        #pragma unroll
        for (int i = 0; i < 8; i++) { G0 += s0[i]; G1 += s1[i]; }
        G0 += bgm[0] + gi[2 * b + 0];
        G1 += bgm[1] + gi[2 * b + 1] + 1.0f;
        igs = 1.f / (1.f + expf(-G0));
        fgs = 1.f / (1.f + expf(-G1));
    }
    __syncthreads();
    const float ig = igs, fg = fgs;

    float* orow = out + (size_t)b * (S_ * M_) + s * M_;
    for (int m = tid; m < M_; m += 256) {
        orow[m] = fmaf(ig, tanhf(m2row[m]), fg * mrow[m]);
    }
}

// ---------------------------------------------------------------------------
// kernel_launch
// ---------------------------------------------------------------------------
extern "C" void kernel_launch(void* const* d_in, const int* in_sizes, int n_in,
                              void* d_out, int out_size)
{
    const float* inputs   = (const float*)d_in[0];
    const float* memory   = (const float*)d_in[1];
    const float* k_qkv    = (const float*)d_in[2];
    const float* b_qkv    = (const float*)d_in[3];
    const float* k_gi     = (const float*)d_in[4];
    const float* b_gi     = (const float*)d_in[5];
    const float* k_gm     = (const float*)d_in[6];
    const float* b_gm     = (const float*)d_in[7];
    const float* k_in     = (const float*)d_in[8];
    const float* b_in     = (const float*)d_in[9];
    const float* mlp_k0   = (const float*)d_in[10];
    const float* mlp_b0   = (const float*)d_in[11];
    const float* mlp_k1   = (const float*)d_in[12];
    const float* mlp_b1   = (const float*)d_in[13];
    float* out = (float*)d_out;

    float *px, *pqkv, *pm2, *pgi;
    bf16 *pinh, *pinl, *pwh, *pwl, *pmpih, *pmpil, *pm1h, *pm1l, *phh, *phl;
    cudaGetSymbolAddress((void**)&px,    g_x);
    cudaGetSymbolAddress((void**)&pqkv,  g_qkv);
    cudaGetSymbolAddress((void**)&pm2,   g_m2);
    cudaGetSymbolAddress((void**)&pgi,   g_gi);
    cudaGetSymbolAddress((void**)&pinh,  g_in_hi);
    cudaGetSymbolAddress((void**)&pinl,  g_in_lo);
    cudaGetSymbolAddress((void**)&pwh,   g_w_hi);
    cudaGetSymbolAddress((void**)&pwl,   g_w_lo);
    cudaGetSymbolAddress((void**)&pmpih, g_mpi_hi);
    cudaGetSymbolAddress((void**)&pmpil, g_mpi_lo);
    cudaGetSymbolAddress((void**)&pm1h,  g_m1_hi);
    cudaGetSymbolAddress((void**)&pm1l,  g_m1_lo);
    cudaGetSymbolAddress((void**)&phh,   g_h_hi);
    cudaGetSymbolAddress((void**)&phl,   g_h_lo);

    const size_t MM = (size_t)M_ * M_;
    bf16 *kinH = pwh,          *kinL = pwl;
    bf16 *kqkH = pwh + MM,     *kqkL = pwl + MM;
    bf16 *k0H  = pwh + 4 * MM, *k0L  = pwl + 4 * MM;
    bf16 *k1H  = pwh + 5 * MM, *k1L  = pwl + 5 * MM;

    cudaFuncSetAttribute(hgemm_kernel<0>, cudaFuncAttributeMaxDynamicSharedMemorySize, DSMEM);
    cudaFuncSetAttribute(hgemm_kernel<1>, cudaFuncAttributeMaxDynamicSharedMemorySize, DSMEM);
    cudaFuncSetAttribute(hgemm_kernel<2>, cudaFuncAttributeMaxDynamicSharedMemorySize, DSMEM);

    // 0. split weights + inputs
    split_kernel<<<(B_ * M_ / 4 + 255) / 256, 256>>>(inputs, pinh, pinl, B_ * M_ / 4);
    split_kernel<<<(int)((MM / 4 + 255) / 256), 256>>>(k_in,   kinH, kinL, (int)(MM / 4));
    split_kernel<<<(int)((3 * MM / 4 + 255) / 256), 256>>>(k_qkv, kqkH, kqkL, (int)(3 * MM / 4));
    split_kernel<<<(int)((MM / 4 + 255) / 256), 256>>>(mlp_k0, k0H, k0L, (int)(MM / 4));
    split_kernel<<<(int)((MM / 4 + 255) / 256), 256>>>(mlp_k1, k1H, k1L, (int)(MM / 4));

    // 1. x = inputs @ kernel_in + bias_in
    hgemm_kernel<0><<<dim3(M_ / 128, B_ / 128), 512, DSMEM>>>(
        pinh, pinl, kinH, kinL, b_in, nullptr, nullptr, px, nullptr, nullptr, M_, M_);

    // 2. mpi (split)
    build_mpi_kernel<<<(unsigned)(((size_t)ROWS_ * M_ / 2) / 256), 256>>>(
        memory, px, pmpih, pmpil);

    // 3. gi
    gi_kernel<<<B_ / 8, 256>>>(px, k_gi, b_gi, pgi);

    // 4. qkv = mpi @ kernel_qkv + bias_qkv
    hgemm_kernel<0><<<dim3(TOT_ / 128, ROWS_ / 128), 512, DSMEM>>>(
        pmpih, pmpil, kqkH, kqkL, b_qkv, nullptr, nullptr, pqkv, nullptr, nullptr, TOT_, M_);

    // 5. attention + residual -> m1 (split)
    attn_kernel<<<B_ * H_, 256>>>(pqkv, pmpih, pmpil, pm1h, pm1l);

    // 6. h = relu(m1 @ mlp_k0 + mlp_b0) -> split
    hgemm_kernel<1><<<dim3(M_ / 128, ROWS_ / 128), 512, DSMEM>>>(
        pm1h, pm1l, k0H, k0L, mlp_b0, nullptr, nullptr, nullptr, phh, phl, M_, M_);

    // 7. m2 = m1 + h @ mlp_k1 + mlp_b1
    hgemm_kernel<2><<<dim3(M_ / 128, ROWS_ / 128), 512, DSMEM>>>(
        phh, phl, k1H, k1L, mlp_b1, pm1h, pm1l, pm2, nullptr, nullptr, M_, M_);

    // 8. gates + output
    gate_kernel<<<B_ * S_, 256>>>(memory, pm2, k_gm, b_gm, pgi, out);
}

// round 8
// speedup vs baseline: 1.9969x; 1.4130x over previous
#include <cuda_runtime.h>
#include <cuda_fp16.h>
#include <math.h>
#include <stdint.h>

// ---------------------------------------------------------------------------
// RelationalMemoryCell  (B=2048, S=8, H=8, M=1024, QKV=384, TOT=3072)
// Round 8: 2-term fp16 HMMA GEMM on the R4 substrate.
//   A (activations) split to fp16 hi+lo;  B (weights) single fp16.
//   D = Ah*Bh + Al*Bh  (= A*Bh, fp32 accumulate; error = weight rounding 2^-11)
// ---------------------------------------------------------------------------

#define B_     2048
#define S_     8
#define H_     8
#define M_     1024
#define QKV_   384
#define TOT_   3072
#define SP1_   9
#define ROWS_  (B_*SP1_)   // 18432

typedef __half  fp16;
typedef __half2 fp162;

// ---- global scratch (allocation-free rule) ----
__device__ __align__(256) float g_x   [(size_t)B_   * M_  ];
__device__ __align__(256) float g_qkv [(size_t)ROWS_* TOT_];
__device__ __align__(256) float g_m2  [(size_t)ROWS_* M_  ];
__device__ __align__(256) float g_gi  [(size_t)B_ * 2];

__device__ __align__(256) fp16 g_in_hi [(size_t)B_ * M_];
__device__ __align__(256) fp16 g_in_lo [(size_t)B_ * M_];
// weights arena (single fp16): k_in @0 (1M), k_qkv @1M (3M), mlp_k0 @4M, mlp_k1 @5M
__device__ __align__(256) fp16 g_w     [(size_t)6 * M_ * M_];
__device__ __align__(256) fp16 g_mpi_hi [(size_t)ROWS_ * M_];
__device__ __align__(256) fp16 g_mpi_lo [(size_t)ROWS_ * M_];
__device__ __align__(256) fp16 g_m1_hi  [(size_t)ROWS_ * M_];
__device__ __align__(256) fp16 g_m1_lo  [(size_t)ROWS_ * M_];
__device__ __align__(256) fp16 g_h_hi   [(size_t)ROWS_ * M_];
__device__ __align__(256) fp16 g_h_lo   [(size_t)ROWS_ * M_];

// ---------------------------------------------------------------------------
// helpers
// ---------------------------------------------------------------------------
__device__ __forceinline__ uint32_t smem_u32(const void* p) {
    uint32_t a;
    asm("{ .reg .u64 t; cvta.to.shared.u64 t, %1; cvt.u32.u64 %0, t; }"
        : "=r"(a) : "l"(p));
    return a;
}
__device__ __forceinline__ void cp16(uint32_t dst, const void* src) {
    asm volatile("cp.async.cg.shared.global [%0], [%1], 16;"
                 :: "r"(dst), "l"(src) : "memory");
}
#define CP_COMMIT() asm volatile("cp.async.commit_group;" ::: "memory")
#define CP_WAIT()   asm volatile("cp.async.wait_group 2;"  ::: "memory")

__device__ __forceinline__ void ldsm4(uint32_t* r, uint32_t a) {
    asm volatile("ldmatrix.sync.aligned.m8n8.x4.shared.b16 {%0,%1,%2,%3}, [%4];"
        : "=r"(r[0]), "=r"(r[1]), "=r"(r[2]), "=r"(r[3]) : "r"(a));
}
__device__ __forceinline__ void ldsm4t(uint32_t* r, uint32_t a) {
    asm volatile("ldmatrix.sync.aligned.m8n8.x4.trans.shared.b16 {%0,%1,%2,%3}, [%4];"
        : "=r"(r[0]), "=r"(r[1]), "=r"(r[2]), "=r"(r[3]) : "r"(a));
}
__device__ __forceinline__ void mma16816(float* c, const uint32_t* a, const uint32_t* b) {
    asm volatile(
        "mma.sync.aligned.m16n8k16.row.col.f32.f16.f16.f32 "
        "{%0,%1,%2,%3}, {%4,%5,%6,%7}, {%8,%9}, {%0,%1,%2,%3};"
        : "+f"(c[0]), "+f"(c[1]), "+f"(c[2]), "+f"(c[3])
        : "r"(a[0]), "r"(a[1]), "r"(a[2]), "r"(a[3]), "r"(b[0]), "r"(b[1]));
}
__device__ __forceinline__ void split1(float v, fp16& hi, fp16& lo) {
    hi = __float2half_rn(v);
    lo = __float2half_rn(v - __half2float(hi));
}

// ---------------------------------------------------------------------------
// split_kernel: fp32 -> (hi, lo) fp16     cvt_kernel: fp32 -> fp16
// ---------------------------------------------------------------------------
__global__ void split_kernel(const float* __restrict__ src,
                             fp16* __restrict__ hi, fp16* __restrict__ lo,
                             int n4)
{
    int i = blockIdx.x * blockDim.x + threadIdx.x;
    if (i >= n4) return;
    float4 v = __ldg((const float4*)src + i);
    fp16 h0, h1, h2, h3, l0, l1, l2, l3;
    split1(v.x, h0, l0); split1(v.y, h1, l1);
    split1(v.z, h2, l2); split1(v.w, h3, l3);
    fp162* H = (fp162*)hi + 2 * i;
    fp162* L = (fp162*)lo + 2 * i;
    H[0] = fp162(h0, h1); H[1] = fp162(h2, h3);
    L[0] = fp162(l0, l1); L[1] = fp162(l2, l3);
}

__global__ void cvt_kernel(const float* __restrict__ src,
                           fp16* __restrict__ dst, int n4)
{
    int i = blockIdx.x * blockDim.x + threadIdx.x;
    if (i >= n4) return;
    float4 v = __ldg((const float4*)src + i);
    fp162* D = (fp162*)dst + 2 * i;
    D[0] = __floats2half2_rn(v.x, v.y);
    D[1] = __floats2half2_rn(v.z, v.w);
}

// ---------------------------------------------------------------------------
// 2-term fp16 HMMA GEMM, 512 threads (16 warps, 4x4 grid, 32x32 warp tile),
// 128x128 CTA tile, BK=32, 4-stage cp.async pipeline.
// MODE 0: fp32 out (+bias)
// MODE 1: relu(+bias) -> split fp16 out (Chi/Clo)
// MODE 2: fp32 out = (Rhi+Rlo) + (+bias)
// SMEM per buffer: Ahi 128x80B @0, Alo @10240, Bh 32x272B @20480  (29184 B)
// ---------------------------------------------------------------------------
#define AST     80u
#define BST     272u
#define OFF_ALO 10240u
#define OFF_BH  20480u
#define BUFSZ   29184u
#define NSTAGE  4
#define DSMEM   (NSTAGE * 29184)

template<int MODE>
__global__ __launch_bounds__(512)
void hgemm_kernel(const fp16* __restrict__ Ahi, const fp16* __restrict__ Alo,
                  const fp16* __restrict__ Bh,
                  const float* __restrict__ bias,
                  const fp16* __restrict__ Rhi, const fp16* __restrict__ Rlo,
                  float* __restrict__ Cf,
                  fp16* __restrict__ Chi, fp16* __restrict__ Clo,
                  int N, int K)
{
    extern __shared__ char sm_[];
    const uint32_t sbase = smem_u32(sm_);

    const int tid  = threadIdx.x;
    const int wid  = tid >> 5;
    const int lane = tid & 31;
    const int wm   = (wid & 3) << 5;     // 0,32,64,96
    const int wn   = (wid >> 2) << 5;    // 0,32,64,96
    const int bm   = blockIdx.y << 7;
    const int bn   = blockIdx.x << 7;

    // loader slots: A 128 rows x 4 segs of 16B; B 32 rows x 16 segs of 16B
    const int arow = tid >> 2, aseg = tid & 3;
    const int brow = tid >> 4, bseg = tid & 15;

    const fp16* ApH = Ahi + (size_t)(bm + arow) * K + (aseg << 3);
    const fp16* ApL = Alo + (size_t)(bm + arow) * K + (aseg << 3);
    const fp16* Bp  = Bh  + (size_t)brow * N + bn + (bseg << 3);
    const uint32_t aDst = (uint32_t)arow * AST + (uint32_t)(aseg << 4);
    const uint32_t bDst = (uint32_t)brow * BST + (uint32_t)(bseg << 4);

    const int nchunk = K >> 5;

    float acc[2][4][4];
    #pragma unroll
    for (int i = 0; i < 2; i++)
        #pragma unroll
        for (int j = 0; j < 4; j++)
            #pragma unroll
            for (int k = 0; k < 4; k++) acc[i][j][k] = 0.f;

    // prologue: stages 0..2
    #pragma unroll
    for (int s = 0; s < NSTAGE - 1; s++) {
        const uint32_t sb = sbase + (uint32_t)s * BUFSZ;
        cp16(sb + aDst,           ApH + (s << 5));
        cp16(sb + OFF_ALO + aDst, ApL + (s << 5));
        cp16(sb + OFF_BH  + bDst, Bp + (size_t)(s << 5) * N);
        CP_COMMIT();
    }

    const uint32_t aOffBase = (uint32_t)(wm + (lane & 15)) * AST
                            + (uint32_t)((lane >> 4) << 4);
    const uint32_t bOffBase = (uint32_t)(lane & 15) * BST
                            + (uint32_t)(wn << 1) + (uint32_t)((lane >> 4) << 4);

    #pragma unroll 1
    for (int c = 0; c < nchunk; c++) {
        CP_WAIT();
        __syncthreads();

        const uint32_t tb = sbase + (uint32_t)(c % NSTAGE) * BUFSZ;

        #pragma unroll
        for (int ks = 0; ks < 2; ks++) {
            uint32_t raH[2][4], raL[2][4], rbH[2][4];
            const uint32_t aAd = tb + aOffBase + (uint32_t)(ks << 5);
            ldsm4(raH[0], aAd);
            ldsm4(raH[1], aAd + 16u * AST);
            ldsm4(raL[0], aAd + OFF_ALO);
            ldsm4(raL[1], aAd + OFF_ALO + 16u * AST);
            const uint32_t bAd = tb + bOffBase + (uint32_t)(ks << 4) * BST;
            ldsm4t(rbH[0], bAd + OFF_BH);
            ldsm4t(rbH[1], bAd + OFF_BH + 32u);
            #pragma unroll
            for (int mt = 0; mt < 2; mt++)
                #pragma unroll
                for (int nt = 0; nt < 4; nt++) {
                    const uint32_t* rb = &rbH[nt >> 1][(nt & 1) << 1];
                    mma16816(acc[mt][nt], raH[mt], rb);
                    mma16816(acc[mt][nt], raL[mt], rb);
                }
        }

        // issue stage c + NSTAGE-1
        const int cn = c + NSTAGE - 1;
        if (cn < nchunk) {
            const uint32_t nb = sbase + (uint32_t)(cn % NSTAGE) * BUFSZ;
            cp16(nb + aDst,           ApH + (cn << 5));
            cp16(nb + OFF_ALO + aDst, ApL + (cn << 5));
            cp16(nb + OFF_BH  + bDst, Bp + (size_t)(cn << 5) * N);
        }
        CP_COMMIT();
    }

    // ---- epilogue ----
    #pragma unroll
    for (int mt = 0; mt < 2; mt++) {
        #pragma unroll
        for (int nt = 0; nt < 4; nt++) {
            const int m = bm + wm + (mt << 4) + (lane >> 2);
            const int n = bn + wn + (nt << 3) + ((lane & 3) << 1);
            const float b0 = __ldg(&bias[n]);
            const float b1 = __ldg(&bias[n + 1]);
            float2 v0, v1;
            v0.x = acc[mt][nt][0] + b0;  v0.y = acc[mt][nt][1] + b1;
            v1.x = acc[mt][nt][2] + b0;  v1.y = acc[mt][nt][3] + b1;
            const size_t i0 = (size_t)m * N + n;
            const size_t i1 = (size_t)(m + 8) * N + n;
            if (MODE == 0) {
                *(float2*)(Cf + i0) = v0;
                *(float2*)(Cf + i1) = v1;
            }
            if (MODE == 1) {
                v0.x = fmaxf(v0.x, 0.f); v0.y = fmaxf(v0.y, 0.f);
                v1.x = fmaxf(v1.x, 0.f); v1.y = fmaxf(v1.y, 0.f);
                fp16 h0, h1, l0, l1;
                split1(v0.x, h0, l0); split1(v0.y, h1, l1);
                *(fp162*)(Chi + i0) = fp162(h0, h1);
                *(fp162*)(Clo + i0) = fp162(l0, l1);
                split1(v1.x, h0, l0); split1(v1.y, h1, l1);
                *(fp162*)(Chi + i1) = fp162(h0, h1);
                *(fp162*)(Clo + i1) = fp162(l0, l1);
            }
            if (MODE == 2) {
                fp162 rh0 = *(const fp162*)(Rhi + i0);
                fp162 rl0 = *(const fp162*)(Rlo + i0);
                fp162 rh1 = *(const fp162*)(Rhi + i1);
                fp162 rl1 = *(const fp162*)(Rlo + i1);
                v0.x += __half2float(rh0.x) + __half2float(rl0.x);
                v0.y += __half2float(rh0.y) + __half2float(rl0.y);
                v1.x += __half2float(rh1.x) + __half2float(rl1.x);
                v1.y += __half2float(rh1.y) + __half2float(rl1.y);
                *(float2*)(Cf + i0) = v0;
                *(float2*)(Cf + i1) = v1;
            }
        }
    }
}

// ---------------------------------------------------------------------------
// mpi(hi/lo) = split(concat(memory, x))
// ---------------------------------------------------------------------------
__global__ void build_mpi_kernel(const float* __restrict__ mem,
                                 const float* __restrict__ x,
                                 fp16* __restrict__ hi, fp16* __restrict__ lo)
{
    size_t i = (size_t)blockIdx.x * blockDim.x + threadIdx.x;
    int    mp  = (int)(i & 511);
    size_t row = i >> 9;
    size_t b   = row / SP1_;
    int    s   = (int)(row - b * SP1_);
    const float* src = (s < S_) ? (mem + ((b * S_ + s) << 10)) : (x + (b << 10));
    float2 v = *(const float2*)(src + (mp << 1));
    fp16 h0, h1, l0, l1;
    split1(v.x, h0, l0); split1(v.y, h1, l1);
    ((fp162*)hi)[i] = fp162(h0, h1);
    ((fp162*)lo)[i] = fp162(l0, l1);
}

// ---------------------------------------------------------------------------
// gi[b,0:2] = x[b,:] @ kernel_gi + bias_gi
// ---------------------------------------------------------------------------
__global__ void gi_kernel(const float* __restrict__ x,
                          const float* __restrict__ kgi,
                          const float* __restrict__ bgi,
                          float* __restrict__ gi)
{
    int b    = blockIdx.x * 8 + (threadIdx.x >> 5);
    int lane = threadIdx.x & 31;
    const float* xr = x + (size_t)b * M_;
    float g0 = 0.f, g1 = 0.f;
    for (int m = lane; m < M_; m += 32) {
        float xv = xr[m];
        g0 = fmaf(xv, kgi[2 * m + 0], g0);
        g1 = fmaf(xv, kgi[2 * m + 1], g1);
    }
    #pragma unroll
    for (int o = 16; o; o >>= 1) {
        g0 += __shfl_xor_sync(0xffffffffu, g0, o);
        g1 += __shfl_xor_sync(0xffffffffu, g1, o);
    }
    if (lane == 0) {
        gi[2 * b + 0] = g0 + bgi[0];
        gi[2 * b + 1] = g1 + bgi[1];
    }
}

// ---------------------------------------------------------------------------
// Attention per (b,h):  m1 = (mpi_hi+mpi_lo) + softmax(q k^T) v -> split out
// ---------------------------------------------------------------------------
__global__ __launch_bounds__(256)
void attn_kernel(const float* __restrict__ qkv,
                 const fp16* __restrict__ mpihi, const fp16* __restrict__ mpilo,
                 fp16* __restrict__ m1hi, fp16* __restrict__ m1lo)
{
    const int bh = blockIdx.x;
    const int b  = bh >> 3;
    const int h  = bh & 7;

    __shared__ float q [SP1_][128];
    __shared__ float kk[SP1_][128];
    __shared__ float vv[SP1_][128];
    __shared__ float sc[SP1_][SP1_];

    const float scale = rsqrtf((float)QKV_);
    const int tid = threadIdx.x;

    for (int i = tid; i < SP1_ * 128; i += 256) {
        int s = i >> 7, d = i & 127;
        const float* base = qkv + ((size_t)(b * SP1_ + s)) * TOT_ + h * QKV_;
        q [s][d] = base[d] * scale;
        kk[s][d] = base[128 + d];
        vv[s][d] = base[256 + d];
    }
    __syncthreads();

    const int w = tid >> 5, lane = tid & 31;
    for (int idx = w; idx < SP1_ * SP1_; idx += 8) {
        int i = idx / SP1_, j = idx - i * SP1_;
        float s = 0.f;
        for (int d = lane; d < 128; d += 32) s = fmaf(q[i][d], kk[j][d], s);
        #pragma unroll
        for (int o = 16; o; o >>= 1) s += __shfl_xor_sync(0xffffffffu, s, o);
        if (lane == 0) sc[i][j] = s;
    }
    __syncthreads();

    if (tid < SP1_) {
        float mx = -1e30f;
        #pragma unroll
        for (int j = 0; j < SP1_; j++) mx = fmaxf(mx, sc[tid][j]);
        float e[SP1_], sum = 0.f;
        #pragma unroll
        for (int j = 0; j < SP1_; j++) { e[j] = expf(sc[tid][j] - mx); sum += e[j]; }
        float inv = 1.f / sum;
        #pragma unroll
        for (int j = 0; j < SP1_; j++) sc[tid][j] = e[j] * inv;
    }
    __syncthreads();

    for (int i = tid; i < SP1_ * 64; i += 256) {
        int s  = i >> 6;
        int d  = (i & 63) << 1;
        float a0 = 0.f, a1 = 0.f;
        #pragma unroll
        for (int j = 0; j < SP1_; j++) {
            a0 = fmaf(sc[s][j], vv[j][d],     a0);
            a1 = fmaf(sc[s][j], vv[j][d + 1], a1);
        }
        size_t o = ((size_t)(b * SP1_ + s)) * M_ + h * 128 + d;
        fp162 mh = *(const fp162*)(mpihi + o);
        fp162 ml = *(const fp162*)(mpilo + o);
        float v0 = __half2float(mh.x) + __half2float(ml.x) + a0;
        float v1 = __half2float(mh.y) + __half2float(ml.y) + a1;
        fp16 h0, h1, l0, l1;
        split1(v0, h0, l0); split1(v1, h1, l1);
        *(fp162*)(m1hi + o) = fp162(h0, h1);
        *(fp162*)(m1lo + o) = fp162(l0, l1);
    }
}

// ---------------------------------------------------------------------------
// Gate epilogue per (b,s)
// ---------------------------------------------------------------------------
__global__ __launch_bounds__(256)
void gate_kernel(const float* __restrict__ mem,
                 const float* __restrict__ m2,
                 const float* __restrict__ kgm,
                 const float* __restrict__ bgm,
                 const float* __restrict__ gi,
                 float* __restrict__ out)
{
    const int bs = blockIdx.x;
    const int b  = bs >> 3;
    const int s  = bs & 7;
    const int tid = threadIdx.x;

    const float* mrow  = mem + (size_t)bs * M_;
    const float* m2row = m2  + ((size_t)(b * SP1_ + s)) * M_;

    float g0 = 0.f, g1 = 0.f;
    for (int m = tid; m < M_; m += 256) {
        float t = tanhf(mrow[m]);
        g0 = fmaf(t, kgm[2 * m + 0], g0);
        g1 = fmaf(t, kgm[2 * m + 1], g1);
    }
    #pragma unroll
    for (int o = 16; o; o >>= 1) {
        g0 += __shfl_xor_sync(0xffffffffu, g0, o);
        g1 += __shfl_xor_sync(0xffffffffu, g1, o);
    }
    __shared__ float s0[8], s1[8];
    __shared__ float igs, fgs;
    int w = tid >> 5, lane = tid & 31;
    if (lane == 0) { s0[w] = g0; s1[w] = g1; }
    __syncthreads();
    if (tid == 0) {
        float G0 = 0.f, G1 = 0.f;
        #pragma unroll
        for (int i = 0; i < 8; i++) { G0 += s0[i]; G1 += s1[i]; }
        G0 += bgm[0] + gi[2 * b + 0];
        G1 += bgm[1] + gi[2 * b + 1] + 1.0f;
        igs = 1.f / (1.f + expf(-G0));
        fgs = 1.f / (1.f + expf(-G1));
    }
    __syncthreads();
    const float ig = igs, fg = fgs;

    float* orow = out + (size_t)b * (S_ * M_) + s * M_;
    for (int m = tid; m < M_; m += 256) {
        orow[m] = fmaf(ig, tanhf(m2row[m]), fg * mrow[m]);
    }
}

// ---------------------------------------------------------------------------
// kernel_launch
// ---------------------------------------------------------------------------
extern "C" void kernel_launch(void* const* d_in, const int* in_sizes, int n_in,
                              void* d_out, int out_size)
{
    const float* inputs   = (const float*)d_in[0];
    const float* memory   = (const float*)d_in[1];
    const float* k_qkv    = (const float*)d_in[2];
    const float* b_qkv    = (const float*)d_in[3];
    const float* k_gi     = (const float*)d_in[4];
    const float* b_gi     = (const float*)d_in[5];
    const float* k_gm     = (const float*)d_in[6];
    const float* b_gm     = (const float*)d_in[7];
    const float* k_in     = (const float*)d_in[8];
    const float* b_in     = (const float*)d_in[9];
    const float* mlp_k0   = (const float*)d_in[10];
    const float* mlp_b0   = (const float*)d_in[11];
    const float* mlp_k1   = (const float*)d_in[12];
    const float* mlp_b1   = (const float*)d_in[13];
    float* out = (float*)d_out;

    float *px, *pqkv, *pm2, *pgi;
    fp16 *pinh, *pinl, *pw, *pmpih, *pmpil, *pm1h, *pm1l, *phh, *phl;
    cudaGetSymbolAddress((void**)&px,    g_x);
    cudaGetSymbolAddress((void**)&pqkv,  g_qkv);
    cudaGetSymbolAddress((void**)&pm2,   g_m2);
    cudaGetSymbolAddress((void**)&pgi,   g_gi);
    cudaGetSymbolAddress((void**)&pinh,  g_in_hi);
    cudaGetSymbolAddress((void**)&pinl,  g_in_lo);
    cudaGetSymbolAddress((void**)&pw,    g_w);
    cudaGetSymbolAddress((void**)&pmpih, g_mpi_hi);
    cudaGetSymbolAddress((void**)&pmpil, g_mpi_lo);
    cudaGetSymbolAddress((void**)&pm1h,  g_m1_hi);
    cudaGetSymbolAddress((void**)&pm1l,  g_m1_lo);
    cudaGetSymbolAddress((void**)&phh,   g_h_hi);
    cudaGetSymbolAddress((void**)&phl,   g_h_lo);

    const size_t MM = (size_t)M_ * M_;
    fp16 *kinW = pw;
    fp16 *kqkW = pw + MM;
    fp16 *k0W  = pw + 4 * MM;
    fp16 *k1W  = pw + 5 * MM;

    cudaFuncSetAttribute(hgemm_kernel<0>, cudaFuncAttributeMaxDynamicSharedMemorySize, DSMEM);
    cudaFuncSetAttribute(hgemm_kernel<1>, cudaFuncAttributeMaxDynamicSharedMemorySize, DSMEM);
    cudaFuncSetAttribute(hgemm_kernel<2>, cudaFuncAttributeMaxDynamicSharedMemorySize, DSMEM);

    // 0. convert weights (single fp16) + split inputs (hi/lo fp16)
    split_kernel<<<(B_ * M_ / 4 + 255) / 256, 256>>>(inputs, pinh, pinl, B_ * M_ / 4);
    cvt_kernel<<<(int)((MM / 4 + 255) / 256), 256>>>(k_in,   kinW, (int)(MM / 4));
    cvt_kernel<<<(int)((3 * MM / 4 + 255) / 256), 256>>>(k_qkv, kqkW, (int)(3 * MM / 4));
    cvt_kernel<<<(int)((MM / 4 + 255) / 256), 256>>>(mlp_k0, k0W, (int)(MM / 4));
    cvt_kernel<<<(int)((MM / 4 + 255) / 256), 256>>>(mlp_k1, k1W, (int)(MM / 4));

    // 1. x = inputs @ kernel_in + bias_in
    hgemm_kernel<0><<<dim3(M_ / 128, B_ / 128), 512, DSMEM>>>(
        pinh, pinl, kinW, b_in, nullptr, nullptr, px, nullptr, nullptr, M_, M_);

    // 2. mpi (split)
    build_mpi_kernel<<<(unsigned)(((size_t)ROWS_ * M_ / 2) / 256), 256>>>(
        memory, px, pmpih, pmpil);

    // 3. gi
    gi_kernel<<<B_ / 8, 256>>>(px, k_gi, b_gi, pgi);

    // 4. qkv = mpi @ kernel_qkv + bias_qkv
    hgemm_kernel<0><<<dim3(TOT_ / 128, ROWS_ / 128), 512, DSMEM>>>(
        pmpih, pmpil, kqkW, b_qkv, nullptr, nullptr, pqkv, nullptr, nullptr, TOT_, M_);

    // 5. attention + residual -> m1 (split)
    attn_kernel<<<B_ * H_, 256>>>(pqkv, pmpih, pmpil, pm1h, pm1l);

    // 6. h = relu(m1 @ mlp_k0 + mlp_b0) -> split
    hgemm_kernel<1><<<dim3(M_ / 128, ROWS_ / 128), 512, DSMEM>>>(
        pm1h, pm1l, k0W, mlp_b0, nullptr, nullptr, nullptr, phh, phl, M_, M_);

    // 7. m2 = m1 + h @ mlp_k1 + mlp_b1
    hgemm_kernel<2><<<dim3(M_ / 128, ROWS_ / 128), 512, DSMEM>>>(
        phh, phl, k1W, mlp_b1, pm1h, pm1l, pm2, nullptr, nullptr, M_, M_);

    // 8. gates + output
    gate_kernel<<<B_ * S_, 256>>>(memory, pm2, k_gm, b_gm, pgi, out);
}

// round 9
// speedup vs baseline: 3.2465x; 1.6257x over previous
#include <cuda_runtime.h>
#include <cuda_fp16.h>
#include <math.h>
#include <stdint.h>

// ---------------------------------------------------------------------------
// RelationalMemoryCell  (B=2048, S=8, H=8, M=1024, QKV=384, TOT=3072)
// Round 9: pure fp16 HMMA GEMM (1 MMA term), fp32 residual paths.
//   All GEMM operands rounded to fp16; accumulate fp32.
//   Residuals (mpi into m1, m1 into m2) carried in fp32 — rounding only
//   enters via GEMM operands where it averages over K=1024.
// ---------------------------------------------------------------------------

#define B_     2048
#define S_     8
#define H_     8
#define M_     1024
#define QKV_   384
#define TOT_   3072
#define SP1_   9
#define ROWS_  (B_*SP1_)   // 18432

typedef __half  fp16;
typedef __half2 fp162;

// ---- global scratch (allocation-free rule) ----
__device__ __align__(256) float g_x   [(size_t)B_   * M_  ];
__device__ __align__(256) float g_qkv [(size_t)ROWS_* TOT_];
__device__ __align__(256) float g_m1f [(size_t)ROWS_* M_  ];
__device__ __align__(256) float g_m2  [(size_t)ROWS_* M_  ];
__device__ __align__(256) float g_gi  [(size_t)B_ * 2];

__device__ __align__(256) fp16 g_in_h  [(size_t)B_ * M_];
// weights arena (fp16): k_in @0 (1M), k_qkv @1M (3M), mlp_k0 @4M, mlp_k1 @5M
__device__ __align__(256) fp16 g_w     [(size_t)6 * M_ * M_];
__device__ __align__(256) fp16 g_mpi_h [(size_t)ROWS_ * M_];
__device__ __align__(256) fp16 g_m1_h  [(size_t)ROWS_ * M_];
__device__ __align__(256) fp16 g_h_h   [(size_t)ROWS_ * M_];

// ---------------------------------------------------------------------------
// helpers
// ---------------------------------------------------------------------------
__device__ __forceinline__ uint32_t smem_u32(const void* p) {
    uint32_t a;
    asm("{ .reg .u64 t; cvta.to.shared.u64 t, %1; cvt.u32.u64 %0, t; }"
        : "=r"(a) : "l"(p));
    return a;
}
__device__ __forceinline__ void cp16(uint32_t dst, const void* src) {
    asm volatile("cp.async.cg.shared.global [%0], [%1], 16;"
                 :: "r"(dst), "l"(src) : "memory");
}
#define CP_COMMIT() asm volatile("cp.async.commit_group;" ::: "memory")
#define CP_WAIT()   asm volatile("cp.async.wait_group 3;"  ::: "memory")

__device__ __forceinline__ void ldsm4(uint32_t* r, uint32_t a) {
    asm volatile("ldmatrix.sync.aligned.m8n8.x4.shared.b16 {%0,%1,%2,%3}, [%4];"
        : "=r"(r[0]), "=r"(r[1]), "=r"(r[2]), "=r"(r[3]) : "r"(a));
}
__device__ __forceinline__ void ldsm4t(uint32_t* r, uint32_t a) {
    asm volatile("ldmatrix.sync.aligned.m8n8.x4.trans.shared.b16 {%0,%1,%2,%3}, [%4];"
        : "=r"(r[0]), "=r"(r[1]), "=r"(r[2]), "=r"(r[3]) : "r"(a));
}
__device__ __forceinline__ void mma16816(float* c, const uint32_t* a, const uint32_t* b) {
    asm volatile(
        "mma.sync.aligned.m16n8k16.row.col.f32.f16.f16.f32 "
        "{%0,%1,%2,%3}, {%4,%5,%6,%7}, {%8,%9}, {%0,%1,%2,%3};"
        : "+f"(c[0]), "+f"(c[1]), "+f"(c[2]), "+f"(c[3])
        : "r"(a[0]), "r"(a[1]), "r"(a[2]), "r"(a[3]), "r"(b[0]), "r"(b[1]));
}

// ---------------------------------------------------------------------------
// cvt_kernel: fp32 -> fp16, vectorized by 4.
// ---------------------------------------------------------------------------
__global__ void cvt_kernel(const float* __restrict__ src,
                           fp16* __restrict__ dst, int n4)
{
    int i = blockIdx.x * blockDim.x + threadIdx.x;
    if (i >= n4) return;
    float4 v = __ldg((const float4*)src + i);
    fp162* D = (fp162*)dst + 2 * i;
    D[0] = __floats2half2_rn(v.x, v.y);
    D[1] = __floats2half2_rn(v.z, v.w);
}

// ---------------------------------------------------------------------------
// fp16 HMMA GEMM, 512 threads (16 warps, 4x4 grid, 32x32 warp tile),
// 128x128 CTA tile, BK=32, 5-stage cp.async pipeline.
// MODE 0: fp32 out (+bias)
// MODE 1: relu(+bias) -> fp16 out (Ch)
// MODE 2: fp32 out = Rf + (+bias)       (Rf = fp32 residual)
// SMEM per buffer: A 128x80B @0, B 32x272B @10240   (18944 B)
// ---------------------------------------------------------------------------
#define AST     80u
#define BST     272u
#define OFF_B   10240u
#define BUFSZ   18944u
#define NSTAGE  5
#define DSMEM   (NSTAGE * 18944)

template<int MODE>
__global__ __launch_bounds__(512)
void hgemm_kernel(const fp16* __restrict__ Ah, const fp16* __restrict__ Bh,
                  const float* __restrict__ bias,
                  const float* __restrict__ Rf,
                  float* __restrict__ Cf, fp16* __restrict__ Ch,
                  int N, int K)
{
    extern __shared__ char sm_[];
    const uint32_t sbase = smem_u32(sm_);

    const int tid  = threadIdx.x;
    const int wid  = tid >> 5;
    const int lane = tid & 31;
    const int wm   = (wid & 3) << 5;     // 0,32,64,96
    const int wn   = (wid >> 2) << 5;    // 0,32,64,96
    const int bm   = blockIdx.y << 7;
    const int bn   = blockIdx.x << 7;

    // loader slots: A 128 rows x 4 segs of 16B (512); B 32 rows x 16 segs (512)
    const int arow = tid >> 2, aseg = tid & 3;
    const int brow = tid >> 4, bseg = tid & 15;

    const fp16* Ap = Ah + (size_t)(bm + arow) * K + (aseg << 3);
    const fp16* Bp = Bh + (size_t)brow * N + bn + (bseg << 3);
    const uint32_t aDst = (uint32_t)arow * AST + (uint32_t)(aseg << 4);
    const uint32_t bDst = (uint32_t)brow * BST + (uint32_t)(bseg << 4);

    const int nchunk = K >> 5;

    float acc[2][4][4];
    #pragma unroll
    for (int i = 0; i < 2; i++)
        #pragma unroll
        for (int j = 0; j < 4; j++)
            #pragma unroll
            for (int k = 0; k < 4; k++) acc[i][j][k] = 0.f;

    // prologue: stages 0..NSTAGE-2
    #pragma unroll
    for (int s = 0; s < NSTAGE - 1; s++) {
        const uint32_t sb = sbase + (uint32_t)s * BUFSZ;
        cp16(sb + aDst,         Ap + (s << 5));
        cp16(sb + OFF_B + bDst, Bp + (size_t)(s << 5) * N);
        CP_COMMIT();
    }

    const uint32_t aOffBase = (uint32_t)(wm + (lane & 15)) * AST
                            + (uint32_t)((lane >> 4) << 4);
    const uint32_t bOffBase = (uint32_t)(lane & 15) * BST
                            + (uint32_t)(wn << 1) + (uint32_t)((lane >> 4) << 4);

    #pragma unroll 1
    for (int c = 0; c < nchunk; c++) {
        CP_WAIT();
        __syncthreads();

        const uint32_t tb = sbase + (uint32_t)(c % NSTAGE) * BUFSZ;

        #pragma unroll
        for (int ks = 0; ks < 2; ks++) {
            uint32_t ra[2][4], rb[2][4];
            const uint32_t aAd = tb + aOffBase + (uint32_t)(ks << 5);
            ldsm4(ra[0], aAd);
            ldsm4(ra[1], aAd + 16u * AST);
            const uint32_t bAd = tb + OFF_B + bOffBase + (uint32_t)(ks << 4) * BST;
            ldsm4t(rb[0], bAd);
            ldsm4t(rb[1], bAd + 32u);
            #pragma unroll
            for (int mt = 0; mt < 2; mt++)
                #pragma unroll
                for (int nt = 0; nt < 4; nt++)
                    mma16816(acc[mt][nt], ra[mt], &rb[nt >> 1][(nt & 1) << 1]);
        }

        // issue stage c + NSTAGE-1
        const int cn = c + NSTAGE - 1;
        if (cn < nchunk) {
            const uint32_t nb = sbase + (uint32_t)(cn % NSTAGE) * BUFSZ;
            cp16(nb + aDst,         Ap + (cn << 5));
            cp16(nb + OFF_B + bDst, Bp + (size_t)(cn << 5) * N);
        }
        CP_COMMIT();
    }

    // ---- epilogue ----
    #pragma unroll
    for (int mt = 0; mt < 2; mt++) {
        #pragma unroll
        for (int nt = 0; nt < 4; nt++) {
            const int m = bm + wm + (mt << 4) + (lane >> 2);
            const int n = bn + wn + (nt << 3) + ((lane & 3) << 1);
            const float b0 = __ldg(&bias[n]);
            const float b1 = __ldg(&bias[n + 1]);
            float2 v0, v1;
            v0.x = acc[mt][nt][0] + b0;  v0.y = acc[mt][nt][1] + b1;
            v1.x = acc[mt][nt][2] + b0;  v1.y = acc[mt][nt][3] + b1;
            const size_t i0 = (size_t)m * N + n;
            const size_t i1 = (size_t)(m + 8) * N + n;
            if (MODE == 0) {
                *(float2*)(Cf + i0) = v0;
                *(float2*)(Cf + i1) = v1;
            }
            if (MODE == 1) {
                v0.x = fmaxf(v0.x, 0.f); v0.y = fmaxf(v0.y, 0.f);
                v1.x = fmaxf(v1.x, 0.f); v1.y = fmaxf(v1.y, 0.f);
                *(fp162*)(Ch + i0) = __floats2half2_rn(v0.x, v0.y);
                *(fp162*)(Ch + i1) = __floats2half2_rn(v1.x, v1.y);
            }
            if (MODE == 2) {
                float2 r0 = *(const float2*)(Rf + i0);
                float2 r1 = *(const float2*)(Rf + i1);
                v0.x += r0.x; v0.y += r0.y;
                v1.x += r1.x; v1.y += r1.y;
                *(float2*)(Cf + i0) = v0;
                *(float2*)(Cf + i1) = v1;
            }
        }
    }
}

// ---------------------------------------------------------------------------
// mpi_h = fp16(concat(memory, x))
// ---------------------------------------------------------------------------
__global__ void build_mpi_kernel(const float* __restrict__ mem,
                                 const float* __restrict__ x,
                                 fp16* __restrict__ hi)
{
    size_t i = (size_t)blockIdx.x * blockDim.x + threadIdx.x;  // pair index
    int    mp  = (int)(i & 511);
    size_t row = i >> 9;
    size_t b   = row / SP1_;
    int    s   = (int)(row - b * SP1_);
    const float* src = (s < S_) ? (mem + ((b * S_ + s) << 10)) : (x + (b << 10));
    float2 v = *(const float2*)(src + (mp << 1));
    ((fp162*)hi)[i] = __floats2half2_rn(v.x, v.y);
}

// ---------------------------------------------------------------------------
// gi[b,0:2] = x[b,:] @ kernel_gi + bias_gi
// ---------------------------------------------------------------------------
__global__ void gi_kernel(const float* __restrict__ x,
                          const float* __restrict__ kgi,
                          const float* __restrict__ bgi,
                          float* __restrict__ gi)
{
    int b    = blockIdx.x * 8 + (threadIdx.x >> 5);
    int lane = threadIdx.x & 31;
    const float* xr = x + (size_t)b * M_;
    float g0 = 0.f, g1 = 0.f;
    for (int m = lane; m < M_; m += 32) {
        float xv = xr[m];
        g0 = fmaf(xv, kgi[2 * m + 0], g0);
        g1 = fmaf(xv, kgi[2 * m + 1], g1);
    }
    #pragma unroll
    for (int o = 16; o; o >>= 1) {
        g0 += __shfl_xor_sync(0xffffffffu, g0, o);
        g1 += __shfl_xor_sync(0xffffffffu, g1, o);
    }
    if (lane == 0) {
        gi[2 * b + 0] = g0 + bgi[0];
        gi[2 * b + 1] = g1 + bgi[1];
    }
}

// ---------------------------------------------------------------------------
// Attention per (b,h): m1 = res + softmax(q k^T) v
//   residual read straight from fp32 memory/x (no fp16 round-trip).
//   writes m1 fp16 (GEMM A input) and m1 fp32 (m2 residual).
// ---------------------------------------------------------------------------
__global__ __launch_bounds__(256)
void attn_kernel(const float* __restrict__ qkv,
                 const float* __restrict__ mem,
                 const float* __restrict__ x,
                 fp16* __restrict__ m1h, float* __restrict__ m1f)
{
    const int bh = blockIdx.x;
    const int b  = bh >> 3;
    const int h  = bh & 7;

    __shared__ float q [SP1_][128];
    __shared__ float kk[SP1_][128];
    __shared__ float vv[SP1_][128];
    __shared__ float sc[SP1_][SP1_];

    const float scale = rsqrtf((float)QKV_);
    const int tid = threadIdx.x;

    for (int i = tid; i < SP1_ * 128; i += 256) {
        int s = i >> 7, d = i & 127;
        const float* base = qkv + ((size_t)(b * SP1_ + s)) * TOT_ + h * QKV_;
        q [s][d] = base[d] * scale;
        kk[s][d] = base[128 + d];
        vv[s][d] = base[256 + d];
    }
    __syncthreads();

    const int w = tid >> 5, lane = tid & 31;
    for (int idx = w; idx < SP1_ * SP1_; idx += 8) {
        int i = idx / SP1_, j = idx - i * SP1_;
        float s = 0.f;
        for (int d = lane; d < 128; d += 32) s = fmaf(q[i][d], kk[j][d], s);
        #pragma unroll
        for (int o = 16; o; o >>= 1) s += __shfl_xor_sync(0xffffffffu, s, o);
        if (lane == 0) sc[i][j] = s;
    }
    __syncthreads();

    if (tid < SP1_) {
        float mx = -1e30f;
        #pragma unroll
        for (int j = 0; j < SP1_; j++) mx = fmaxf(mx, sc[tid][j]);
        float e[SP1_], sum = 0.f;
        #pragma unroll
        for (int j = 0; j < SP1_; j++) { e[j] = expf(sc[tid][j] - mx); sum += e[j]; }
        float inv = 1.f / sum;
        #pragma unroll
        for (int j = 0; j < SP1_; j++) sc[tid][j] = e[j] * inv;
    }
    __syncthreads();

    for (int i = tid; i < SP1_ * 64; i += 256) {
        int s  = i >> 6;
        int d  = (i & 63) << 1;
        float a0 = 0.f, a1 = 0.f;
        #pragma unroll
        for (int j = 0; j < SP1_; j++) {
            a0 = fmaf(sc[s][j], vv[j][d],     a0);
            a1 = fmaf(sc[s][j], vv[j][d + 1], a1);
        }
        const float* src = (s < S_) ? (mem + (((size_t)b * S_ + s) << 10))
                                    : (x + ((size_t)b << 10));
        float2 r = *(const float2*)(src + h * 128 + d);
        float v0 = r.x + a0;
        float v1 = r.y + a1;
        size_t o = ((size_t)(b * SP1_ + s)) * M_ + h * 128 + d;
        *(fp162*)(m1h + o) = __floats2half2_rn(v0, v1);
        *(float2*)(m1f + o) = make_float2(v0, v1);
    }
}

// ---------------------------------------------------------------------------
// Gate epilogue per (b,s)
// ---------------------------------------------------------------------------
__global__ __launch_bounds__(256)
void gate_kernel(const float* __restrict__ mem,
                 const float* __restrict__ m2,
                 const float* __restrict__ kgm,
                 const float* __restrict__ bgm,
                 const float* __restrict__ gi,
                 float* __restrict__ out)
{
    const int bs = blockIdx.x;
    const int b  = bs >> 3;
    const int s  = bs & 7;
    const int tid = threadIdx.x;

    const float* mrow  = mem + (size_t)bs * M_;
    const float* m2row = m2  + ((size_t)(b * SP1_ + s)) * M_;

    float g0 = 0.f, g1 = 0.f;
    for (int m = tid; m < M_; m += 256) {
        float t = tanhf(mrow[m]);
        g0 = fmaf(t, kgm[2 * m + 0], g0);
        g1 = fmaf(t, kgm[2 * m + 1], g1);
    }
    #pragma unroll
    for (int o = 16; o; o >>= 1) {
        g0 += __shfl_xor_sync(0xffffffffu, g0, o);
        g1 += __shfl_xor_sync(0xffffffffu, g1, o);
    }
    __shared__ float s0[8], s1[8];
    __shared__ float igs, fgs;
    int w = tid >> 5, lane = tid & 31;
    if (lane == 0) { s0[w] = g0; s1[w] = g1; }
    __syncthreads();
    if (tid == 0) {
        float G0 = 0.f, G1 = 0.f;
        #pragma unroll
        for (int i = 0; i < 8; i++) { G0 += s0[i]; G1 += s1[i]; }
        G0 += bgm[0] + gi[2 * b + 0];
        G1 += bgm[1] + gi[2 * b + 1] + 1.0f;
        igs = 1.f / (1.f + expf(-G0));
        fgs = 1.f / (1.f + expf(-G1));
    }
    __syncthreads();
    const float ig = igs, fg = fgs;

    float* orow = out + (size_t)b * (S_ * M_) + s * M_;
    for (int m = tid; m < M_; m += 256) {
        orow[m] = fmaf(ig, tanhf(m2row[m]), fg * mrow[m]);
    }
}

// ---------------------------------------------------------------------------
// kernel_launch
// ---------------------------------------------------------------------------
extern "C" void kernel_launch(void* const* d_in, const int* in_sizes, int n_in,
                              void* d_out, int out_size)
{
    const float* inputs   = (const float*)d_in[0];
    const float* memory   = (const float*)d_in[1];
    const float* k_qkv    = (const float*)d_in[2];
    const float* b_qkv    = (const float*)d_in[3];
    const float* k_gi     = (const float*)d_in[4];
    const float* b_gi     = (const float*)d_in[5];
    const float* k_gm     = (const float*)d_in[6];
    const float* b_gm     = (const float*)d_in[7];
    const float* k_in     = (const float*)d_in[8];
    const float* b_in     = (const float*)d_in[9];
    const float* mlp_k0   = (const float*)d_in[10];
    const float* mlp_b0   = (const float*)d_in[11];
    const float* mlp_k1   = (const float*)d_in[12];
    const float* mlp_b1   = (const float*)d_in[13];
    float* out = (float*)d_out;

    float *px, *pqkv, *pm1f, *pm2, *pgi;
    fp16 *pinh, *pw, *pmpih, *pm1h, *phh;
    cudaGetSymbolAddress((void**)&px,    g_x);
    cudaGetSymbolAddress((void**)&pqkv,  g_qkv);
    cudaGetSymbolAddress((void**)&pm1f,  g_m1f);
    cudaGetSymbolAddress((void**)&pm2,   g_m2);
    cudaGetSymbolAddress((void**)&pgi,   g_gi);
    cudaGetSymbolAddress((void**)&pinh,  g_in_h);
    cudaGetSymbolAddress((void**)&pw,    g_w);
    cudaGetSymbolAddress((void**)&pmpih, g_mpi_h);
    cudaGetSymbolAddress((void**)&pm1h,  g_m1_h);
    cudaGetSymbolAddress((void**)&phh,   g_h_h);

    const size_t MM = (size_t)M_ * M_;
    fp16 *kinW = pw;
    fp16 *kqkW = pw + MM;
    fp16 *k0W  = pw + 4 * MM;
    fp16 *k1W  = pw + 5 * MM;

    cudaFuncSetAttribute(hgemm_kernel<0>, cudaFuncAttributeMaxDynamicSharedMemorySize, DSMEM);
    cudaFuncSetAttribute(hgemm_kernel<1>, cudaFuncAttributeMaxDynamicSharedMemorySize, DSMEM);
    cudaFuncSetAttribute(hgemm_kernel<2>, cudaFuncAttributeMaxDynamicSharedMemorySize, DSMEM);

    // 0. convert inputs + weights to fp16
    cvt_kernel<<<(B_ * M_ / 4 + 255) / 256, 256>>>(inputs, pinh, B_ * M_ / 4);
    cvt_kernel<<<(int)((MM / 4 + 255) / 256), 256>>>(k_in,   kinW, (int)(MM / 4));
    cvt_kernel<<<(int)((3 * MM / 4 + 255) / 256), 256>>>(k_qkv, kqkW, (int)(3 * MM / 4));
    cvt_kernel<<<(int)((MM / 4 + 255) / 256), 256>>>(mlp_k0, k0W, (int)(MM / 4));
    cvt_kernel<<<(int)((MM / 4 + 255) / 256), 256>>>(mlp_k1, k1W, (int)(MM / 4));

    // 1. x = inputs @ kernel_in + bias_in
    hgemm_kernel<0><<<dim3(M_ / 128, B_ / 128), 512, DSMEM>>>(
        pinh, kinW, b_in, nullptr, px, nullptr, M_, M_);

    // 2. mpi (fp16)
    build_mpi_kernel<<<(unsigned)(((size_t)ROWS_ * M_ / 2) / 256), 256>>>(
        memory, px, pmpih);

    // 3. gi
    gi_kernel<<<B_ / 8, 256>>>(px, k_gi, b_gi, pgi);

    // 4. qkv = mpi @ kernel_qkv + bias_qkv
    hgemm_kernel<0><<<dim3(TOT_ / 128, ROWS_ / 128), 512, DSMEM>>>(
        pmpih, kqkW, b_qkv, nullptr, pqkv, nullptr, TOT_, M_);

    // 5. attention + fp32 residual -> m1 (fp16 + fp32)
    attn_kernel<<<B_ * H_, 256>>>(pqkv, memory, px, pm1h, pm1f);

    // 6. h = relu(m1 @ mlp_k0 + mlp_b0) -> fp16
    hgemm_kernel<1><<<dim3(M_ / 128, ROWS_ / 128), 512, DSMEM>>>(
        pm1h, k0W, mlp_b0, nullptr, nullptr, phh, M_, M_);

    // 7. m2 = m1(fp32) + h @ mlp_k1 + mlp_b1
    hgemm_kernel<2><<<dim3(M_ / 128, ROWS_ / 128), 512, DSMEM>>>(
        phh, k1W, mlp_b1, pm1f, pm2, nullptr, M_, M_);

    // 8. gates + output
    gate_kernel<<<B_ * S_, 256>>>(memory, pm2, k_gm, b_gm, pgi, out);
}

// round 10
// speedup vs baseline: 3.2913x; 1.0138x over previous
#include <cuda_runtime.h>
#include <cuda_fp16.h>
#include <math.h>
#include <stdint.h>

// ---------------------------------------------------------------------------
// RelationalMemoryCell  (B=2048, S=8, H=8, M=1024, QKV=384, TOT=3072)
// Round 10: R9 + BK=64 (half the barrier rounds) + fp16 qkv intermediate.
//   Pure fp16 HMMA (1 term), fp32 accumulate, fp32 residual paths.
// ---------------------------------------------------------------------------

#define B_     2048
#define S_     8
#define H_     8
#define M_     1024
#define QKV_   384
#define TOT_   3072
#define SP1_   9
#define ROWS_  (B_*SP1_)   // 18432

typedef __half  fp16;
typedef __half2 fp162;

// ---- global scratch (allocation-free rule) ----
__device__ __align__(256) float g_x   [(size_t)B_   * M_  ];
__device__ __align__(256) float g_m1f [(size_t)ROWS_* M_  ];
__device__ __align__(256) float g_m2  [(size_t)ROWS_* M_  ];
__device__ __align__(256) float g_gi  [(size_t)B_ * 2];

__device__ __align__(256) fp16 g_qkv_h [(size_t)ROWS_ * TOT_];
__device__ __align__(256) fp16 g_in_h  [(size_t)B_ * M_];
// weights arena (fp16): k_in @0 (1M), k_qkv @1M (3M), mlp_k0 @4M, mlp_k1 @5M
__device__ __align__(256) fp16 g_w     [(size_t)6 * M_ * M_];
__device__ __align__(256) fp16 g_mpi_h [(size_t)ROWS_ * M_];
__device__ __align__(256) fp16 g_m1_h  [(size_t)ROWS_ * M_];
__device__ __align__(256) fp16 g_h_h   [(size_t)ROWS_ * M_];

// ---------------------------------------------------------------------------
// helpers
// ---------------------------------------------------------------------------
__device__ __forceinline__ uint32_t smem_u32(const void* p) {
    uint32_t a;
    asm("{ .reg .u64 t; cvta.to.shared.u64 t, %1; cvt.u32.u64 %0, t; }"
        : "=r"(a) : "l"(p));
    return a;
}
__device__ __forceinline__ void cp16(uint32_t dst, const void* src) {
    asm volatile("cp.async.cg.shared.global [%0], [%1], 16;"
                 :: "r"(dst), "l"(src) : "memory");
}
#define CP_COMMIT() asm volatile("cp.async.commit_group;" ::: "memory")
#define CP_WAIT()   asm volatile("cp.async.wait_group 1;"  ::: "memory")

__device__ __forceinline__ void ldsm4(uint32_t* r, uint32_t a) {
    asm volatile("ldmatrix.sync.aligned.m8n8.x4.shared.b16 {%0,%1,%2,%3}, [%4];"
        : "=r"(r[0]), "=r"(r[1]), "=r"(r[2]), "=r"(r[3]) : "r"(a));
}
__device__ __forceinline__ void ldsm4t(uint32_t* r, uint32_t a) {
    asm volatile("ldmatrix.sync.aligned.m8n8.x4.trans.shared.b16 {%0,%1,%2,%3}, [%4];"
        : "=r"(r[0]), "=r"(r[1]), "=r"(r[2]), "=r"(r[3]) : "r"(a));
}
__device__ __forceinline__ void mma16816(float* c, const uint32_t* a, const uint32_t* b) {
    asm volatile(
        "mma.sync.aligned.m16n8k16.row.col.f32.f16.f16.f32 "
        "{%0,%1,%2,%3}, {%4,%5,%6,%7}, {%8,%9}, {%0,%1,%2,%3};"
        : "+f"(c[0]), "+f"(c[1]), "+f"(c[2]), "+f"(c[3])
        : "r"(a[0]), "r"(a[1]), "r"(a[2]), "r"(a[3]), "r"(b[0]), "r"(b[1]));
}

// ---------------------------------------------------------------------------
// cvt_kernel: fp32 -> fp16, vectorized by 4.
// ---------------------------------------------------------------------------
__global__ void cvt_kernel(const float* __restrict__ src,
                           fp16* __restrict__ dst, int n4)
{
    int i = blockIdx.x * blockDim.x + threadIdx.x;
    if (i >= n4) return;
    float4 v = __ldg((const float4*)src + i);
    fp162* D = (fp162*)dst + 2 * i;
    D[0] = __floats2half2_rn(v.x, v.y);
    D[1] = __floats2half2_rn(v.z, v.w);
}

// ---------------------------------------------------------------------------
// fp16 HMMA GEMM, 512 threads (16 warps, 4x4 grid, 32x32 warp tile),
// 128x128 CTA tile, BK=64, 3-stage cp.async pipeline.
// MODE 0: fp32 out (+bias)
// MODE 1: relu(+bias) -> fp16 out (Ch)
// MODE 2: fp32 out = Rf + (+bias)
// MODE 3: fp16 out (+bias)
// SMEM per buffer: A 128x144B @0 (18432), B 64x272B @18432 (17408) = 35840 B
// ---------------------------------------------------------------------------
#define AST     144u
#define BST     272u
#define OFF_B   18432u
#define BUFSZ   35840u
#define NSTAGE  3
#define DSMEM   (NSTAGE * 35840)

template<int MODE>
__global__ __launch_bounds__(512)
void hgemm_kernel(const fp16* __restrict__ Ah, const fp16* __restrict__ Bh,
                  const float* __restrict__ bias,
                  const float* __restrict__ Rf,
                  float* __restrict__ Cf, fp16* __restrict__ Ch,
                  int N, int K)
{
    extern __shared__ char sm_[];
    const uint32_t sbase = smem_u32(sm_);

    const int tid  = threadIdx.x;
    const int wid  = tid >> 5;
    const int lane = tid & 31;
    const int wm   = (wid & 3) << 5;     // 0,32,64,96
    const int wn   = (wid >> 2) << 5;    // 0,32,64,96
    const int bm   = blockIdx.y << 7;
    const int bn   = blockIdx.x << 7;

    // loader slots (2 iters each):
    // A: 128 rows x 8 segs of 16B (1024 slots)
    // B: 64 rows x 16 segs of 16B (1024 slots)
    const int arow = tid >> 2, aseg = tid & 3;       // segs aseg, aseg+4
    const int brow = tid >> 4, bseg = tid & 15;      // rows brow, brow+32

    const fp16* Ap = Ah + (size_t)(bm + arow) * K + (aseg << 3);
    const fp16* Bp = Bh + (size_t)brow * N + bn + (bseg << 3);
    const uint32_t aDst  = (uint32_t)arow * AST + (uint32_t)(aseg << 4);
    const uint32_t bDst  = (uint32_t)brow * BST + (uint32_t)(bseg << 4);
    const size_t  bRow2  = (size_t)32 * N;
    const uint32_t bDst2 = bDst + 32u * BST;

    const int nchunk = K >> 6;

    float acc[2][4][4];
    #pragma unroll
    for (int i = 0; i < 2; i++)
        #pragma unroll
        for (int j = 0; j < 4; j++)
            #pragma unroll
            for (int k = 0; k < 4; k++) acc[i][j][k] = 0.f;

    // prologue: stages 0..NSTAGE-2
    #pragma unroll
    for (int s = 0; s < NSTAGE - 1; s++) {
        const uint32_t sb = sbase + (uint32_t)s * BUFSZ;
        cp16(sb + aDst,        Ap + (s << 6));
        cp16(sb + aDst + 64u,  Ap + (s << 6) + 32);
        cp16(sb + OFF_B + bDst,  Bp + (size_t)(s << 6) * N);
        cp16(sb + OFF_B + bDst2, Bp + bRow2 + (size_t)(s << 6) * N);
        CP_COMMIT();
    }

    const uint32_t aOffBase = (uint32_t)(wm + (lane & 15)) * AST
                            + (uint32_t)((lane >> 4) << 4);
    const uint32_t bOffBase = (uint32_t)(lane & 15) * BST
                            + (uint32_t)(wn << 1) + (uint32_t)((lane >> 4) << 4);

    #pragma unroll 1
    for (int c = 0; c < nchunk; c++) {
        CP_WAIT();
        __syncthreads();

        const uint32_t tb = sbase + (uint32_t)(c % NSTAGE) * BUFSZ;

        #pragma unroll
        for (int ks = 0; ks < 4; ks++) {
            uint32_t ra[2][4], rb[2][4];
            const uint32_t aAd = tb + aOffBase + (uint32_t)(ks << 5);
            ldsm4(ra[0], aAd);
            ldsm4(ra[1], aAd + 16u * AST);
            const uint32_t bAd = tb + OFF_B + bOffBase + (uint32_t)(ks << 4) * BST;
            ldsm4t(rb[0], bAd);
            ldsm4t(rb[1], bAd + 32u);
            #pragma unroll
            for (int mt = 0; mt < 2; mt++)
                #pragma unroll
                for (int nt = 0; nt < 4; nt++)
                    mma16816(acc[mt][nt], ra[mt], &rb[nt >> 1][(nt & 1) << 1]);
        }

        // issue stage c + NSTAGE-1
        const int cn = c + NSTAGE - 1;
        if (cn < nchunk) {
            const uint32_t nb = sbase + (uint32_t)(cn % NSTAGE) * BUFSZ;
            cp16(nb + aDst,        Ap + (cn << 6));
            cp16(nb + aDst + 64u,  Ap + (cn << 6) + 32);
            cp16(nb + OFF_B + bDst,  Bp + (size_t)(cn << 6) * N);
            cp16(nb + OFF_B + bDst2, Bp + bRow2 + (size_t)(cn << 6) * N);
        }
        CP_COMMIT();
    }

    // ---- epilogue ----
    #pragma unroll
    for (int mt = 0; mt < 2; mt++) {
        #pragma unroll
        for (int nt = 0; nt < 4; nt++) {
            const int m = bm + wm + (mt << 4) + (lane >> 2);
            const int n = bn + wn + (nt << 3) + ((lane & 3) << 1);
            const float b0 = __ldg(&bias[n]);
            const float b1 = __ldg(&bias[n + 1]);
            float2 v0, v1;
            v0.x = acc[mt][nt][0] + b0;  v0.y = acc[mt][nt][1] + b1;
            v1.x = acc[mt][nt][2] + b0;  v1.y = acc[mt][nt][3] + b1;
            const size_t i0 = (size_t)m * N + n;
            const size_t i1 = (size_t)(m + 8) * N + n;
            if (MODE == 0) {
                *(float2*)(Cf + i0) = v0;
                *(float2*)(Cf + i1) = v1;
            }
            if (MODE == 1) {
                v0.x = fmaxf(v0.x, 0.f); v0.y = fmaxf(v0.y, 0.f);
                v1.x = fmaxf(v1.x, 0.f); v1.y = fmaxf(v1.y, 0.f);
                *(fp162*)(Ch + i0) = __floats2half2_rn(v0.x, v0.y);
                *(fp162*)(Ch + i1) = __floats2half2_rn(v1.x, v1.y);
            }
            if (MODE == 2) {
                float2 r0 = *(const float2*)(Rf + i0);
                float2 r1 = *(const float2*)(Rf + i1);
                v0.x += r0.x; v0.y += r0.y;
                v1.x += r1.x; v1.y += r1.y;
                *(float2*)(Cf + i0) = v0;
                *(float2*)(Cf + i1) = v1;
            }
            if (MODE == 3) {
                *(fp162*)(Ch + i0) = __floats2half2_rn(v0.x, v0.y);
                *(fp162*)(Ch + i1) = __floats2half2_rn(v1.x, v1.y);
            }
        }
    }
}

// ---------------------------------------------------------------------------
// mpi_h = fp16(concat(memory, x))
// ---------------------------------------------------------------------------
__global__ void build_mpi_kernel(const float* __restrict__ mem,
                                 const float* __restrict__ x,
                                 fp16* __restrict__ hi)
{
    size_t i = (size_t)blockIdx.x * blockDim.x + threadIdx.x;  // pair index
    int    mp  = (int)(i & 511);
    size_t row = i >> 9;
    size_t b   = row / SP1_;
    int    s   = (int)(row - b * SP1_);
    const float* src = (s < S_) ? (mem + ((b * S_ + s) << 10)) : (x + (b << 10));
    float2 v = *(const float2*)(src + (mp << 1));
    ((fp162*)hi)[i] = __floats2half2_rn(v.x, v.y);
}

// ---------------------------------------------------------------------------
// gi[b,0:2] = x[b,:] @ kernel_gi + bias_gi
// ---------------------------------------------------------------------------
__global__ void gi_kernel(const float* __restrict__ x,
                          const float* __restrict__ kgi,
                          const float* __restrict__ bgi,
                          float* __restrict__ gi)
{
    int b    = blockIdx.x * 8 + (threadIdx.x >> 5);
    int lane = threadIdx.x & 31;
    const float* xr = x + (size_t)b * M_;
    float g0 = 0.f, g1 = 0.f;
    for (int m = lane; m < M_; m += 32) {
        float xv = xr[m];
        g0 = fmaf(xv, kgi[2 * m + 0], g0);
        g1 = fmaf(xv, kgi[2 * m + 1], g1);
    }
    #pragma unroll
    for (int o = 16; o; o >>= 1) {
        g0 += __shfl_xor_sync(0xffffffffu, g0, o);
        g1 += __shfl_xor_sync(0xffffffffu, g1, o);
    }
    if (lane == 0) {
        gi[2 * b + 0] = g0 + bgi[0];
        gi[2 * b + 1] = g1 + bgi[1];
    }
}

// ---------------------------------------------------------------------------
// Attention per (b,h): m1 = res + softmax(q k^T) v   (qkv in fp16)
// ---------------------------------------------------------------------------
__global__ __launch_bounds__(256)
void attn_kernel(const fp16* __restrict__ qkv,
                 const float* __restrict__ mem,
                 const float* __restrict__ x,
                 fp16* __restrict__ m1h, float* __restrict__ m1f)
{
    const int bh = blockIdx.x;
    const int b  = bh >> 3;
    const int h  = bh & 7;

    __shared__ float q [SP1_][128];
    __shared__ float kk[SP1_][128];
    __shared__ float vv[SP1_][128];
    __shared__ float sc[SP1_][SP1_];

    const float scale = rsqrtf((float)QKV_);
    const int tid = threadIdx.x;

    for (int i = tid; i < SP1_ * 64; i += 256) {
        int s = i >> 6, d = (i & 63) << 1;
        const fp16* base = qkv + ((size_t)(b * SP1_ + s)) * TOT_ + h * QKV_;
        fp162 qv = *(const fp162*)(base + d);
        fp162 kv = *(const fp162*)(base + 128 + d);
        fp162 vv2 = *(const fp162*)(base + 256 + d);
        q [s][d]     = __half2float(qv.x) * scale;
        q [s][d + 1] = __half2float(qv.y) * scale;
        kk[s][d]     = __half2float(kv.x);
        kk[s][d + 1] = __half2float(kv.y);
        vv[s][d]     = __half2float(vv2.x);
        vv[s][d + 1] = __half2float(vv2.y);
    }
    __syncthreads();

    const int w = tid >> 5, lane = tid & 31;
    for (int idx = w; idx < SP1_ * SP1_; idx += 8) {
        int i = idx / SP1_, j = idx - i * SP1_;
        float s = 0.f;
        for (int d = lane; d < 128; d += 32) s = fmaf(q[i][d], kk[j][d], s);
        #pragma unroll
        for (int o = 16; o; o >>= 1) s += __shfl_xor_sync(0xffffffffu, s, o);
        if (lane == 0) sc[i][j] = s;
    }
    __syncthreads();

    if (tid < SP1_) {
        float mx = -1e30f;
        #pragma unroll
        for (int j = 0; j < SP1_; j++) mx = fmaxf(mx, sc[tid][j]);
        float e[SP1_], sum = 0.f;
        #pragma unroll
        for (int j = 0; j < SP1_; j++) { e[j] = expf(sc[tid][j] - mx); sum += e[j]; }
        float inv = 1.f / sum;
        #pragma unroll
        for (int j = 0; j < SP1_; j++) sc[tid][j] = e[j] * inv;
    }
    __syncthreads();

    for (int i = tid; i < SP1_ * 64; i += 256) {
        int s  = i >> 6;
        int d  = (i & 63) << 1;
        float a0 = 0.f, a1 = 0.f;
        #pragma unroll
        for (int j = 0; j < SP1_; j++) {
            a0 = fmaf(sc[s][j], vv[j][d],     a0);
            a1 = fmaf(sc[s][j], vv[j][d + 1], a1);
        }
        const float* src = (s < S_) ? (mem + (((size_t)b * S_ + s) << 10))
                                    : (x + ((size_t)b << 10));
        float2 r = *(const float2*)(src + h * 128 + d);
        float v0 = r.x + a0;
        float v1 = r.y + a1;
        size_t o = ((size_t)(b * SP1_ + s)) * M_ + h * 128 + d;
        *(fp162*)(m1h + o) = __floats2half2_rn(v0, v1);
        *(float2*)(m1f + o) = make_float2(v0, v1);
    }
}

// ---------------------------------------------------------------------------
// Gate epilogue per (b,s)
// ---------------------------------------------------------------------------
__global__ __launch_bounds__(256)
void gate_kernel(const float* __restrict__ mem,
                 const float* __restrict__ m2,
                 const float* __restrict__ kgm,
                 const float* __restrict__ bgm,
                 const float* __restrict__ gi,
                 float* __restrict__ out)
{
    const int bs = blockIdx.x;
    const int b  = bs >> 3;
    const int s  = bs & 7;
    const int tid = threadIdx.x;

    const float* mrow  = mem + (size_t)bs * M_;
    const float* m2row = m2  + ((size_t)(b * SP1_ + s)) * M_;

    float g0 = 0.f, g1 = 0.f;
    for (int m = tid; m < M_; m += 256) {
        float t = tanhf(mrow[m]);
        g0 = fmaf(t, kgm[2 * m + 0], g0);
        g1 = fmaf(t, kgm[2 * m + 1], g1);
    }
    #pragma unroll
    for (int o = 16; o; o >>= 1) {
        g0 += __shfl_xor_sync(0xffffffffu, g0, o);
        g1 += __shfl_xor_sync(0xffffffffu, g1, o);
    }
    __shared__ float s0[8], s1[8];
    __shared__ float igs, fgs;
    int w = tid >> 5, lane = tid & 31;
    if (lane == 0) { s0[w] = g0; s1[w] = g1; }
    __syncthreads();
    if (tid == 0) {
        float G0 = 0.f, G1 = 0.f;
        #pragma unroll
        for (int i = 0; i < 8; i++) { G0 += s0[i]; G1 += s1[i]; }
        G0 += bgm[0] + gi[2 * b + 0];
        G1 += bgm[1] + gi[2 * b + 1] + 1.0f;
        igs = 1.f / (1.f + expf(-G0));
        fgs = 1.f / (1.f + expf(-G1));
    }
    __syncthreads();
    const float ig = igs, fg = fgs;

    float* orow = out + (size_t)b * (S_ * M_) + s * M_;
    for (int m = tid; m < M_; m += 256) {
        orow[m] = fmaf(ig, tanhf(m2row[m]), fg * mrow[m]);
    }
}

// ---------------------------------------------------------------------------
// kernel_launch
// ---------------------------------------------------------------------------
extern "C" void kernel_launch(void* const* d_in, const int* in_sizes, int n_in,
                              void* d_out, int out_size)
{
    const float* inputs   = (const float*)d_in[0];
    const float* memory   = (const float*)d_in[1];
    const float* k_qkv    = (const float*)d_in[2];
    const float* b_qkv    = (const float*)d_in[3];
    const float* k_gi     = (const float*)d_in[4];
    const float* b_gi     = (const float*)d_in[5];
    const float* k_gm     = (const float*)d_in[6];
    const float* b_gm     = (const float*)d_in[7];
    const float* k_in     = (const float*)d_in[8];
    const float* b_in     = (const float*)d_in[9];
    const float* mlp_k0   = (const float*)d_in[10];
    const float* mlp_b0   = (const float*)d_in[11];
    const float* mlp_k1   = (const float*)d_in[12];
    const float* mlp_b1   = (const float*)d_in[13];
    float* out = (float*)d_out;

    float *px, *pm1f, *pm2, *pgi;
    fp16 *pqkvh, *pinh, *pw, *pmpih, *pm1h, *phh;
    cudaGetSymbolAddress((void**)&px,    g_x);
    cudaGetSymbolAddress((void**)&pm1f,  g_m1f);
    cudaGetSymbolAddress((void**)&pm2,   g_m2);
    cudaGetSymbolAddress((void**)&pgi,   g_gi);
    cudaGetSymbolAddress((void**)&pqkvh, g_qkv_h);
    cudaGetSymbolAddress((void**)&pinh,  g_in_h);
    cudaGetSymbolAddress((void**)&pw,    g_w);
    cudaGetSymbolAddress((void**)&pmpih, g_mpi_h);
    cudaGetSymbolAddress((void**)&pm1h,  g_m1_h);
    cudaGetSymbolAddress((void**)&phh,   g_h_h);

    const size_t MM = (size_t)M_ * M_;
    fp16 *kinW = pw;
    fp16 *kqkW = pw + MM;
    fp16 *k0W  = pw + 4 * MM;
    fp16 *k1W  = pw + 5 * MM;

    cudaFuncSetAttribute(hgemm_kernel<0>, cudaFuncAttributeMaxDynamicSharedMemorySize, DSMEM);
    cudaFuncSetAttribute(hgemm_kernel<1>, cudaFuncAttributeMaxDynamicSharedMemorySize, DSMEM);
    cudaFuncSetAttribute(hgemm_kernel<2>, cudaFuncAttributeMaxDynamicSharedMemorySize, DSMEM);
    cudaFuncSetAttribute(hgemm_kernel<3>, cudaFuncAttributeMaxDynamicSharedMemorySize, DSMEM);

    // 0. convert inputs + weights to fp16
    cvt_kernel<<<(B_ * M_ / 4 + 255) / 256, 256>>>(inputs, pinh, B_ * M_ / 4);
    cvt_kernel<<<(int)((MM / 4 + 255) / 256), 256>>>(k_in,   kinW, (int)(MM / 4));
    cvt_kernel<<<(int)((3 * MM / 4 + 255) / 256), 256>>>(k_qkv, kqkW, (int)(3 * MM / 4));
    cvt_kernel<<<(int)((MM / 4 + 255) / 256), 256>>>(mlp_k0, k0W, (int)(MM / 4));
    cvt_kernel<<<(int)((MM / 4 + 255) / 256), 256>>>(mlp_k1, k1W, (int)(MM / 4));

    // 1. x = inputs @ kernel_in + bias_in   (fp32 out — feeds gi + residuals)
    hgemm_kernel<0><<<dim3(M_ / 128, B_ / 128), 512, DSMEM>>>(
        pinh, kinW, b_in, nullptr, px, nullptr, M_, M_);

    // 2. mpi (fp16)
    build_mpi_kernel<<<(unsigned)(((size_t)ROWS_ * M_ / 2) / 256), 256>>>(
        memory, px, pmpih);

    // 3. gi
    gi_kernel<<<B_ / 8, 256>>>(px, k_gi, b_gi, pgi);

    // 4. qkv = mpi @ kernel_qkv + bias_qkv   (fp16 out)
    hgemm_kernel<3><<<dim3(TOT_ / 128, ROWS_ / 128), 512, DSMEM>>>(
        pmpih, kqkW, b_qkv, nullptr, nullptr, pqkvh, TOT_, M_);

    // 5. attention + fp32 residual -> m1 (fp16 + fp32)
    attn_kernel<<<B_ * H_, 256>>>(pqkvh, memory, px, pm1h, pm1f);

    // 6. h = relu(m1 @ mlp_k0 + mlp_b0) -> fp16
    hgemm_kernel<1><<<dim3(M_ / 128, ROWS_ / 128), 512, DSMEM>>>(
        pm1h, k0W, mlp_b0, nullptr, nullptr, phh, M_, M_);

    // 7. m2 = m1(fp32) + h @ mlp_k1 + mlp_b1
    hgemm_kernel<2><<<dim3(M_ / 128, ROWS_ / 128), 512, DSMEM>>>(
        phh, k1W, mlp_b1, pm1f, pm2, nullptr, M_, M_);

    // 8. gates + output
    gate_kernel<<<B_ * S_, 256>>>(memory, pm2, k_gm, b_gm, pgi, out);
}